// round 9
// baseline (speedup 1.0000x reference)
#include <cuda_runtime.h>
#include <cstdint>
#include <math.h>

#define BB 64
#define SS 256
#define DD 512

// ---------------- scratch (__device__ globals; no allocation) ---------------
__device__ float g_A  [BB * SS * SS];    // A[b][i][j]   (tf32-rounded)
__device__ float g_At [BB * SS * SS];    // A[b][j][i]   (tf32-rounded)
__device__ float g_F0a[BB * SS * DD];
__device__ float g_F1a[BB * SS * DD];
__device__ float g_W0t[DD * SS];         // W0^T [d][k]  (tf32-rounded)
__device__ float g_W1t[DD * SS];
__device__ float g_sq0[BB * SS];
__device__ float g_sq1[BB * SS];

// ---------------- helpers ---------------------------------------------------
__device__ __forceinline__ uint32_t smem_u32(const void* p) {
    uint32_t a;
    asm("{ .reg .u64 t; cvta.to.shared.u64 t, %1; cvt.u32.u64 %0, t; }" : "=r"(a) : "l"(p));
    return a;
}
__device__ __forceinline__ float rtf32(float x) {   // round-to-nearest tf32
    uint32_t u;
    asm("cvt.rna.tf32.f32 %0, %1;" : "=r"(u) : "f"(x));
    return __uint_as_float(u);
}
__device__ __forceinline__ uint32_t lds32(uint32_t a) {
    uint32_t v;
    asm volatile("ld.shared.b32 %0, [%1];" : "=r"(v) : "r"(a));
    return v;
}
#define CP_ASYNC16(dst, src) \
    asm volatile("cp.async.cg.shared.global [%0], [%1], 16;" :: "r"(dst), "l"(src))
#define CP_COMMIT() asm volatile("cp.async.commit_group;" ::: "memory")
#define CP_WAIT1()  asm volatile("cp.async.wait_group 1;" ::: "memory")

__device__ __forceinline__ void mma_tf32(float* c, const uint32_t* a, const uint32_t* b) {
    asm volatile(
        "mma.sync.aligned.m16n8k8.row.col.f32.tf32.tf32.f32 "
        "{%0,%1,%2,%3}, {%4,%5,%6,%7}, {%8,%9}, {%0,%1,%2,%3};"
        : "+f"(c[0]), "+f"(c[1]), "+f"(c[2]), "+f"(c[3])
        : "r"(a[0]), "r"(a[1]), "r"(a[2]), "r"(a[3]), "r"(b[0]), "r"(b[1]));
}

// ---------------------------------------------------------------------------
// Prep kernel: sqnorms (blocks 0..8191, 2 rows each) + W transpose (8192..8447)
// ---------------------------------------------------------------------------
__global__ __launch_bounds__(256) void prep_kernel(
    const float* __restrict__ F0r, const float* __restrict__ F1r,
    const float* __restrict__ m0, const float* __restrict__ m1,
    const float* __restrict__ W0, const float* __restrict__ W1)
{
    __shared__ float sh0[2][4], sh1[2][4];
    __shared__ float t[32][33];
    int bx = blockIdx.x;
    int tid = threadIdx.x;

    if (bx < 8192) {
        int half = tid >> 7, lt = tid & 127;
        int row = bx * 2 + half;
        const float4* r0 = (const float4*)(F0r + (size_t)row * DD);
        const float4* r1 = (const float4*)(F1r + (size_t)row * DD);
        float4 a = r0[lt];
        float4 b = r1[lt];
        float s0 = a.x * a.x + a.y * a.y + a.z * a.z + a.w * a.w;
        float s1 = b.x * b.x + b.y * b.y + b.z * b.z + b.w * b.w;
        #pragma unroll
        for (int o = 16; o > 0; o >>= 1) {
            s0 += __shfl_xor_sync(0xFFFFFFFFu, s0, o);
            s1 += __shfl_xor_sync(0xFFFFFFFFu, s1, o);
        }
        int w = lt >> 5;
        if ((lt & 31) == 0) { sh0[half][w] = s0; sh1[half][w] = s1; }
        __syncthreads();
        if (lt == 0) {
            s0 = sh0[half][0] + sh0[half][1] + sh0[half][2] + sh0[half][3];
            s1 = sh1[half][0] + sh1[half][1] + sh1[half][2] + sh1[half][3];
            g_sq0[row] = s0 * m0[row];
            g_sq1[row] = s1 * m1[row];
        }
    } else {
        int r = bx - 8192;                 // 0..255
        int sel = r >> 7;
        int d0 = (r & 15) * 32;
        int k0 = ((r >> 4) & 7) * 32;
        const float* W = sel ? W1 : W0;
        float* Wt = sel ? g_W1t : g_W0t;
        int tx = tid & 31, ty = tid >> 5;  // 32 x 8
        #pragma unroll
        for (int rr = 0; rr < 32; rr += 8)
            t[ty + rr][tx] = W[(size_t)(k0 + ty + rr) * DD + d0 + tx];
        __syncthreads();
        #pragma unroll
        for (int rr = 0; rr < 32; rr += 8)
            Wt[(size_t)(d0 + ty + rr) * SS + k0 + tx] = rtf32(t[tx][ty + rr]);
    }
}

// ---------------------------------------------------------------------------
// mma.sync tf32 GEMM core.  Block tile 64(m) x 128(n), 256 threads, 8 warps
// in a 2x4 grid, warp tile 32x32.  BK=16, smem rows 16+4 floats (80 B,
// conflict-free).  3-stage cp.async ring, one __syncthreads per k-tile,
// loads 2 tiles ahead.  4 CTAs/SM (regs<=64, smem 46080).
// ---------------------------------------------------------------------------
#define A_BYTES (64 * 80)                  // 5120
#define B_BYTES (128 * 80)                 // 10240
#define STAGE_BYTES (A_BYTES + B_BYTES)    // 15360
#define NSTAGE 3
#define GEMM_SMEM (NSTAGE * STAGE_BYTES)   // 46080

template <int KTOT>
__device__ __forceinline__ void gemm_mainloop(
    const float* __restrict__ Ag, const float* __restrict__ Bg,
    uint32_t sb, int tid, float acc[2][4][4],
    uint32_t aoff, uint32_t boff)
{
    constexpr int T = KTOT / 16;

    auto load_tile = [&](int t, int s) {
        uint32_t ab = sb + s * STAGE_BYTES;
        uint32_t bb = ab + A_BYTES;
        int k0 = t * 16;
        {   // A: 64 rows x 4 parts = 256 chunks, 1/thread
            int row = tid >> 2, part = tid & 3;
            uint32_t doff = (uint32_t)(row * 80 + part * 16);
            CP_ASYNC16(ab + doff, Ag + (size_t)row * KTOT + k0 + part * 4);
        }
        #pragma unroll
        for (int i = 0; i < 2; i++) {   // B: 128 rows x 4 parts = 512 chunks
            int idx = tid + i * 256;
            int row = idx >> 2, part = idx & 3;
            uint32_t doff = (uint32_t)(row * 80 + part * 16);
            CP_ASYNC16(bb + doff, Bg + (size_t)row * KTOT + k0 + part * 4);
        }
    };

    load_tile(0, 0); CP_COMMIT();
    load_tile(1, 1); CP_COMMIT();

    int s = 0;
    for (int t = 0; t < T; t++) {
        CP_WAIT1();           // tile t resident (t+1 may be in flight)
        __syncthreads();      // visibility; slot s+2 reusable
        int lt = t + 2;
        int ls = s + 2; if (ls >= NSTAGE) ls -= NSTAGE;
        if (lt < T) load_tile(lt, ls);
        CP_COMMIT();

        uint32_t ab = sb + s * STAGE_BYTES + aoff;
        uint32_t bb = sb + s * STAGE_BYTES + A_BYTES + boff;
        #pragma unroll
        for (int ks = 0; ks < 2; ks++) {
            uint32_t af[2][4], bf[4][2];
            #pragma unroll
            for (int mf = 0; mf < 2; mf++) {
                uint32_t base = ab + mf * (16 * 80) + ks * 32;
                af[mf][0] = lds32(base);
                af[mf][1] = lds32(base + 8 * 80);
                af[mf][2] = lds32(base + 16);
                af[mf][3] = lds32(base + 8 * 80 + 16);
            }
            #pragma unroll
            for (int nf = 0; nf < 4; nf++) {
                uint32_t base = bb + nf * (8 * 80) + ks * 32;
                bf[nf][0] = lds32(base);
                bf[nf][1] = lds32(base + 16);
            }
            #pragma unroll
            for (int mf = 0; mf < 2; mf++)
                #pragma unroll
                for (int nf = 0; nf < 4; nf++)
                    mma_tf32(acc[mf][nf], af[mf], bf[nf]);
        }
        if (++s >= NSTAGE) s -= NSTAGE;
    }
}

// ---------------------------------------------------------------------------
// GEMM A (attention): cross tile 64x128 of F0 @ F1^T (K=512) -> g_A, g_At
// ---------------------------------------------------------------------------
__global__ __launch_bounds__(256, 4) void gemm_attn(
    const float* __restrict__ F0r, const float* __restrict__ F1r,
    const float* __restrict__ m0_, const float* __restrict__ m1_)
{
    extern __shared__ char smem[];
    const int tid = threadIdx.x;
    const int wid = tid >> 5, lane = tid & 31;
    const int g = lane >> 2, t4 = lane & 3;
    const int wm = wid & 1, wn = wid >> 1;     // 2 x 4 warp grid
    const int b = blockIdx.z, mt = blockIdx.y, nt = blockIdx.x;

    uint32_t sb = smem_u32(smem);
    const float* Ag = F0r + (size_t)b * SS * DD + (size_t)mt * 64 * DD;
    const float* Bg = F1r + (size_t)b * SS * DD + (size_t)nt * 128 * DD;

    float acc[2][4][4];
    #pragma unroll
    for (int i = 0; i < 2; i++)
        #pragma unroll
        for (int j = 0; j < 4; j++)
            #pragma unroll
            for (int r = 0; r < 4; r++) acc[i][j][r] = 0.f;

    const uint32_t aoff = (uint32_t)((wm * 32 + g) * 80 + t4 * 4);
    const uint32_t boff = (uint32_t)((wn * 32 + g) * 80 + t4 * 4);

    gemm_mainloop<512>(Ag, Bg, sb, tid, acc, aoff, boff);

    // -------------------- attention epilogue (single 64x128 pass) -----------
    float* tile = (float*)smem;                         // [64][132] = 33792 B
    float* s_sq0 = (float*)(smem + 33792);              // [64]
    float* s_a0  = s_sq0 + 64;                          // [64] = 2*m0
    float* s_sq1 = s_a0 + 64;                           // [128]
    float* s_m1  = s_sq1 + 128;                         // [128]

    __syncthreads();   // mainloop smem dead
    if (tid < 64) {
        s_sq0[tid] = g_sq0[b * SS + mt * 64 + tid];
        s_a0[tid]  = 2.f * m0_[b * SS + mt * 64 + tid];
    }
    if (tid < 128) {
        s_sq1[tid] = g_sq1[b * SS + nt * 128 + tid];
        s_m1[tid]  = m1_[b * SS + nt * 128 + tid];
    }
    #pragma unroll
    for (int mf = 0; mf < 2; mf++) {
        int lr = wm * 32 + mf * 16 + g;
        #pragma unroll
        for (int nf = 0; nf < 4; nf++) {
            int col = wn * 32 + nf * 8 + 2 * t4;
            *(float2*)&tile[lr * 132 + col] =
                make_float2(acc[mf][nf][0], acc[mf][nf][1]);
            *(float2*)&tile[(lr + 8) * 132 + col] =
                make_float2(acc[mf][nf][2], acc[mf][nf][3]);
        }
    }
    __syncthreads();

    float* Aout  = g_A  + (size_t)b * SS * SS;
    float* Atout = g_At + (size_t)b * SS * SS;

    // pass 1: A row-major (64x128), float4 per thread iter
    #pragma unroll
    for (int it = 0; it < 8; it++) {
        int lin = it * 1024 + tid * 4;
        int row = lin >> 7, col = lin & 127;
        float s0v = s_sq0[row], a0v = s_a0[row];
        float4 cr = *(float4*)&tile[row * 132 + col];
        float d2, v0, v1, v2, v3;
        d2 = fmaxf(s0v + s_sq1[col]     - a0v * s_m1[col]     * cr.x, 0.f);
        v0 = rtf32(1.f / (1.f + sqrtf(d2)));
        d2 = fmaxf(s0v + s_sq1[col + 1] - a0v * s_m1[col + 1] * cr.y, 0.f);
        v1 = rtf32(1.f / (1.f + sqrtf(d2)));
        d2 = fmaxf(s0v + s_sq1[col + 2] - a0v * s_m1[col + 2] * cr.z, 0.f);
        v2 = rtf32(1.f / (1.f + sqrtf(d2)));
        d2 = fmaxf(s0v + s_sq1[col + 3] - a0v * s_m1[col + 3] * cr.w, 0.f);
        v3 = rtf32(1.f / (1.f + sqrtf(d2)));
        *(float4*)&Aout[(size_t)(mt * 64 + row) * SS + nt * 128 + col] =
            make_float4(v0, v1, v2, v3);
    }

    // pass 2: At (transposed), float4 along m
    #pragma unroll
    for (int it = 0; it < 8; it++) {
        int pair = it * 256 + tid;             // 128 cols x 16 rowgroups
        int col = pair >> 4, rg = pair & 15;
        int r0 = rg * 4;
        float s1v = s_sq1[col], m1v = s_m1[col];
        float v[4];
        #pragma unroll
        for (int q = 0; q < 4; q++) {
            int row = r0 + q;
            float cr = tile[row * 132 + col];
            float d2 = fmaxf(s_sq0[row] + s1v - s_a0[row] * m1v * cr, 0.f);
            v[q] = rtf32(1.f / (1.f + sqrtf(d2)));
        }
        *(float4*)&Atout[(size_t)(nt * 128 + col) * SS + mt * 64 + r0] =
            make_float4(v[0], v[1], v[2], v[3]);
    }
}

// ---------------------------------------------------------------------------
// GEMM B (both aggregations).  blockIdx.y: 0..3 -> F0a (At@W0t) mt=y,
// 4..7 -> F1a (A@W1t) mt=y-4.  K=256.  M-tile 64.
// ---------------------------------------------------------------------------
__global__ __launch_bounds__(256, 4) void gemm_aggr(void)
{
    extern __shared__ char smem[];
    const int tid = threadIdx.x;
    const int wid = tid >> 5, lane = tid & 31;
    const int g = lane >> 2, t4 = lane & 3;
    const int wm = wid & 1, wn = wid >> 1;
    const int b = blockIdx.z, nt = blockIdx.x;
    const int sel = blockIdx.y >> 2;          // 0: F0a, 1: F1a
    const int mt  = blockIdx.y & 3;

    uint32_t sb = smem_u32(smem);
    const float* Ag = (sel ? g_A : g_At) + (size_t)b * SS * SS + (size_t)mt * 64 * SS;
    const float* Bg = (sel ? g_W1t : g_W0t) + (size_t)nt * 128 * SS;

    float acc[2][4][4];
    #pragma unroll
    for (int i = 0; i < 2; i++)
        #pragma unroll
        for (int j = 0; j < 4; j++)
            #pragma unroll
            for (int r = 0; r < 4; r++) acc[i][j][r] = 0.f;

    const uint32_t aoff = (uint32_t)((wm * 32 + g) * 80 + t4 * 4);
    const uint32_t boff = (uint32_t)((wn * 32 + g) * 80 + t4 * 4);

    gemm_mainloop<256>(Ag, Bg, sb, tid, acc, aoff, boff);

    float* O = (sel ? g_F1a : g_F0a) + (size_t)b * SS * DD;
    #pragma unroll
    for (int mf = 0; mf < 2; mf++) {
        int m = mt * 64 + wm * 32 + mf * 16 + g;
        #pragma unroll
        for (int nf = 0; nf < 4; nf++) {
            int col = nt * 128 + wn * 32 + nf * 8 + 2 * t4;
            *(float2*)&O[(size_t)m * DD + col] =
                make_float2(acc[mf][nf][0], acc[mf][nf][1]);
            *(float2*)&O[(size_t)(m + 8) * DD + col] =
                make_float2(acc[mf][nf][2], acc[mf][nf][3]);
        }
    }
}

// ---------------------------------------------------------------------------
// Conv (2ch, h=3, pad 2) + bias + tanh + avgpool(3), float2 per thread,
// 8-row segments.  256 threads cover D=512.
// ---------------------------------------------------------------------------
__device__ __forceinline__ float fast_tanh(float x)
{
    float e = __expf(2.f * x);
    return 1.f - __fdividef(2.f, 1.f + e);
}

__global__ __launch_bounds__(256) void conv_kernel(
    const float* __restrict__ F0r, const float* __restrict__ F1r,
    const float* __restrict__ m0, const float* __restrict__ m1,
    const float* __restrict__ conv_w, const float* __restrict__ conv_b,
    float* __restrict__ out)
{
    const int p = blockIdx.y & 1;
    const int b = blockIdx.y >> 1;
    const float* F  = p ? F1r : F0r;
    const float* mk = p ? m1 : m0;
    const float* Fa = p ? g_F1a : g_F0a;
    float* o = out + ((size_t)p * BB + b) * SS * DD;

    const int s0 = blockIdx.x * 8;
    const int d  = threadIdx.x * 2;

    float w0[3], w1[3];
    #pragma unroll
    for (int h = 0; h < 3; h++) { w0[h] = conv_w[h]; w1[h] = conv_w[3 + h]; }
    const float cb = conv_b[0];

    float2 xf[12], xa[12];
    #pragma unroll
    for (int u = 0; u < 12; u++) {
        int t = s0 - 2 + u;
        bool in = (t >= 0) && (t < SS);
        if (in) {
            float mv = mk[b * SS + t];
            float2 f = *(const float2*)&F[((size_t)b * SS + t) * DD + d];
            xf[u] = make_float2(f.x * mv, f.y * mv);
            xa[u] = *(const float2*)&Fa[((size_t)b * SS + t) * DD + d];
        } else {
            xf[u] = make_float2(0.f, 0.f);
            xa[u] = make_float2(0.f, 0.f);
        }
    }

    float2 y[10];
    #pragma unroll
    for (int u = 0; u < 10; u++) {
        float ax = cb, ay = cb;
        #pragma unroll
        for (int h = 0; h < 3; h++) {
            ax += w0[h] * xf[u + h].x + w1[h] * xa[u + h].x;
            ay += w0[h] * xf[u + h].y + w1[h] * xa[u + h].y;
        }
        y[u] = make_float2(fast_tanh(ax), fast_tanh(ay));
    }
    #pragma unroll
    for (int q = 0; q < 8; q++) {
        float2 r = make_float2(
            (y[q].x + y[q + 1].x + y[q + 2].x) * (1.f / 3.f),
            (y[q].y + y[q + 1].y + y[q + 2].y) * (1.f / 3.f));
        *(float2*)&o[(size_t)(s0 + q) * DD + d] = r;
    }
}

// ---------------------------------------------------------------------------
// Launch
// ---------------------------------------------------------------------------
extern "C" void kernel_launch(void* const* d_in, const int* in_sizes, int n_in,
                              void* d_out, int out_size)
{
    const float* F0r    = (const float*)d_in[0];
    const float* F1r    = (const float*)d_in[1];
    const float* m0     = (const float*)d_in[2];
    const float* m1     = (const float*)d_in[3];
    const float* W0     = (const float*)d_in[4];
    const float* W1     = (const float*)d_in[5];
    const float* conv_w = (const float*)d_in[6];
    const float* conv_b = (const float*)d_in[7];
    float* out = (float*)d_out;

    cudaFuncSetAttribute(gemm_attn, cudaFuncAttributeMaxDynamicSharedMemorySize, GEMM_SMEM);
    cudaFuncSetAttribute(gemm_aggr, cudaFuncAttributeMaxDynamicSharedMemorySize, GEMM_SMEM);

    prep_kernel<<<8448, 256>>>(F0r, F1r, m0, m1, W0, W1);

    gemm_attn<<<dim3(2, 4, BB), 256, GEMM_SMEM>>>(F0r, F1r, m0, m1);
    gemm_aggr<<<dim3(4, 8, BB), 256, GEMM_SMEM>>>();

    conv_kernel<<<dim3(32, 2 * BB), 256>>>(F0r, F1r, m0, m1, conv_w, conv_b, out);
}

// round 10
// speedup vs baseline: 1.0109x; 1.0109x over previous
#include <cuda_runtime.h>
#include <cstdint>
#include <math.h>

#define BB 64
#define SS 256
#define DD 512

// ---------------- scratch (__device__ globals; no allocation) ---------------
__device__ float g_A  [BB * SS * SS];    // A[b][i][j]   (tf32-rounded)
__device__ float g_At [BB * SS * SS];    // A[b][j][i]   (tf32-rounded)
__device__ float g_F0a[BB * SS * DD];
__device__ float g_F1a[BB * SS * DD];
__device__ float g_W0t[DD * SS];         // W0^T [d][k]  (tf32-rounded)
__device__ float g_W1t[DD * SS];
__device__ float g_sq0[BB * SS];
__device__ float g_sq1[BB * SS];

// ---------------- helpers ---------------------------------------------------
__device__ __forceinline__ uint32_t smem_u32(const void* p) {
    uint32_t a;
    asm("{ .reg .u64 t; cvta.to.shared.u64 t, %1; cvt.u32.u64 %0, t; }" : "=r"(a) : "l"(p));
    return a;
}
__device__ __forceinline__ float rtf32(float x) {   // round-to-nearest tf32
    uint32_t u;
    asm("cvt.rna.tf32.f32 %0, %1;" : "=r"(u) : "f"(x));
    return __uint_as_float(u);
}
__device__ __forceinline__ uint32_t lds32(uint32_t a) {
    uint32_t v;
    asm volatile("ld.shared.b32 %0, [%1];" : "=r"(v) : "r"(a));
    return v;
}
#define CP_ASYNC16(dst, src) \
    asm volatile("cp.async.cg.shared.global [%0], [%1], 16;" :: "r"(dst), "l"(src))
#define CP_COMMIT() asm volatile("cp.async.commit_group;" ::: "memory")
#define CP_WAIT1()  asm volatile("cp.async.wait_group 1;" ::: "memory")

__device__ __forceinline__ void mma_tf32(float* c, const uint32_t* a, const uint32_t* b) {
    asm volatile(
        "mma.sync.aligned.m16n8k8.row.col.f32.tf32.tf32.f32 "
        "{%0,%1,%2,%3}, {%4,%5,%6,%7}, {%8,%9}, {%0,%1,%2,%3};"
        : "+f"(c[0]), "+f"(c[1]), "+f"(c[2]), "+f"(c[3])
        : "r"(a[0]), "r"(a[1]), "r"(a[2]), "r"(a[3]), "r"(b[0]), "r"(b[1]));
}

// ---------------------------------------------------------------------------
// Prep kernel: sqnorms (blocks 0..8191, 2 rows each) + W transpose (8192..8447)
// ---------------------------------------------------------------------------
__global__ __launch_bounds__(256) void prep_kernel(
    const float* __restrict__ F0r, const float* __restrict__ F1r,
    const float* __restrict__ m0, const float* __restrict__ m1,
    const float* __restrict__ W0, const float* __restrict__ W1)
{
    __shared__ float sh0[2][4], sh1[2][4];
    __shared__ float t[32][33];
    int bx = blockIdx.x;
    int tid = threadIdx.x;

    if (bx < 8192) {
        int half = tid >> 7, lt = tid & 127;
        int row = bx * 2 + half;
        const float4* r0 = (const float4*)(F0r + (size_t)row * DD);
        const float4* r1 = (const float4*)(F1r + (size_t)row * DD);
        float4 a = r0[lt];
        float4 b = r1[lt];
        float s0 = a.x * a.x + a.y * a.y + a.z * a.z + a.w * a.w;
        float s1 = b.x * b.x + b.y * b.y + b.z * b.z + b.w * b.w;
        #pragma unroll
        for (int o = 16; o > 0; o >>= 1) {
            s0 += __shfl_xor_sync(0xFFFFFFFFu, s0, o);
            s1 += __shfl_xor_sync(0xFFFFFFFFu, s1, o);
        }
        int w = lt >> 5;
        if ((lt & 31) == 0) { sh0[half][w] = s0; sh1[half][w] = s1; }
        __syncthreads();
        if (lt == 0) {
            s0 = sh0[half][0] + sh0[half][1] + sh0[half][2] + sh0[half][3];
            s1 = sh1[half][0] + sh1[half][1] + sh1[half][2] + sh1[half][3];
            g_sq0[row] = s0 * m0[row];
            g_sq1[row] = s1 * m1[row];
        }
    } else {
        int r = bx - 8192;                 // 0..255
        int sel = r >> 7;
        int d0 = (r & 15) * 32;
        int k0 = ((r >> 4) & 7) * 32;
        const float* W = sel ? W1 : W0;
        float* Wt = sel ? g_W1t : g_W0t;
        int tx = tid & 31, ty = tid >> 5;  // 32 x 8
        #pragma unroll
        for (int rr = 0; rr < 32; rr += 8)
            t[ty + rr][tx] = W[(size_t)(k0 + ty + rr) * DD + d0 + tx];
        __syncthreads();
        #pragma unroll
        for (int rr = 0; rr < 32; rr += 8)
            Wt[(size_t)(d0 + ty + rr) * SS + k0 + tx] = rtf32(t[tx][ty + rr]);
    }
}

// ---------------------------------------------------------------------------
// mma.sync tf32 GEMM core.  Block tile 128x128, 128 threads, 4 warps in a
// 2x2 grid, warp tile 64x64 (acc 128 regs/lane).  BK=16, smem rows 16+4
// floats (80 B, conflict-free).  3-stage cp.async ring, one __syncthreads
// per k-tile, loads 2 tiles ahead.  2 CTAs/SM.
// ---------------------------------------------------------------------------
#define OPER_BYTES (128 * 80)              // 10240
#define STAGE_BYTES (2 * OPER_BYTES)       // 20480
#define NSTAGE 3
#define GEMM_SMEM (NSTAGE * STAGE_BYTES)   // 61440

template <int KTOT>
__device__ __forceinline__ void gemm_mainloop(
    const float* __restrict__ Ag, const float* __restrict__ Bg,
    uint32_t sb, int tid, float acc[4][8][4],
    uint32_t aoff, uint32_t boff)
{
    constexpr int T = KTOT / 16;

    auto load_tile = [&](int t, int s) {
        uint32_t ab = sb + s * STAGE_BYTES;
        uint32_t bb = ab + OPER_BYTES;
        int k0 = t * 16;
        #pragma unroll
        for (int i = 0; i < 4; i++) {          // 512 chunks each, 4/thread
            int idx = tid + i * 128;
            int row = idx >> 2, part = idx & 3;
            uint32_t doff = (uint32_t)(row * 80 + part * 16);
            CP_ASYNC16(ab + doff, Ag + (size_t)row * KTOT + k0 + part * 4);
            CP_ASYNC16(bb + doff, Bg + (size_t)row * KTOT + k0 + part * 4);
        }
    };

    load_tile(0, 0); CP_COMMIT();
    load_tile(1, 1); CP_COMMIT();

    int s = 0;
    for (int t = 0; t < T; t++) {
        CP_WAIT1();           // tile t resident (t+1 may be in flight)
        __syncthreads();      // visibility; slot s+2 reusable
        int lt = t + 2;
        int ls = s + 2; if (ls >= NSTAGE) ls -= NSTAGE;
        if (lt < T) load_tile(lt, ls);
        CP_COMMIT();

        uint32_t ab = sb + s * STAGE_BYTES + aoff;
        uint32_t bb = sb + s * STAGE_BYTES + OPER_BYTES + boff;
        #pragma unroll
        for (int ks = 0; ks < 2; ks++) {
            uint32_t af[4][4], bf[8][2];
            #pragma unroll
            for (int mf = 0; mf < 4; mf++) {
                uint32_t base = ab + mf * (16 * 80) + ks * 32;
                af[mf][0] = lds32(base);
                af[mf][1] = lds32(base + 8 * 80);
                af[mf][2] = lds32(base + 16);
                af[mf][3] = lds32(base + 8 * 80 + 16);
            }
            #pragma unroll
            for (int nf = 0; nf < 8; nf++) {
                uint32_t base = bb + nf * (8 * 80) + ks * 32;
                bf[nf][0] = lds32(base);
                bf[nf][1] = lds32(base + 16);
            }
            #pragma unroll
            for (int mf = 0; mf < 4; mf++)
                #pragma unroll
                for (int nf = 0; nf < 8; nf++)
                    mma_tf32(acc[mf][nf], af[mf], bf[nf]);
        }
        if (++s >= NSTAGE) s -= NSTAGE;
    }
}

// ---------------------------------------------------------------------------
// GEMM A (attention): cross tile 128x128 of F0 @ F1^T (K=512) -> g_A, g_At
// ---------------------------------------------------------------------------
__global__ __launch_bounds__(128) void gemm_attn(
    const float* __restrict__ F0r, const float* __restrict__ F1r,
    const float* __restrict__ m0_, const float* __restrict__ m1_)
{
    extern __shared__ char smem[];
    const int tid = threadIdx.x;
    const int wid = tid >> 5, lane = tid & 31;
    const int g = lane >> 2, t4 = lane & 3;
    const int wm = wid & 1, wn = wid >> 1;     // 2 x 2 warp grid
    const int b = blockIdx.z, mt = blockIdx.y, nt = blockIdx.x;

    uint32_t sb = smem_u32(smem);
    const float* Ag = F0r + (size_t)b * SS * DD + (size_t)mt * 128 * DD;
    const float* Bg = F1r + (size_t)b * SS * DD + (size_t)nt * 128 * DD;

    float acc[4][8][4];
    #pragma unroll
    for (int i = 0; i < 4; i++)
        #pragma unroll
        for (int j = 0; j < 8; j++)
            #pragma unroll
            for (int r = 0; r < 4; r++) acc[i][j][r] = 0.f;

    const uint32_t aoff = (uint32_t)((wm * 64 + g) * 80 + t4 * 4);
    const uint32_t boff = (uint32_t)((wn * 64 + g) * 80 + t4 * 4);

    gemm_mainloop<512>(Ag, Bg, sb, tid, acc, aoff, boff);

    // -------------------- attention epilogue (two 64-row halves) ------------
    float* tile = (float*)smem;                         // [64][132] = 33792 B
    float* s_sq0 = (float*)(smem + 33792);              // [128]
    float* s_a0  = s_sq0 + 128;                         // [128] = 2*m0
    float* s_sq1 = s_a0 + 128;                          // [128]
    float* s_m1  = s_sq1 + 128;                         // [128]

    __syncthreads();   // mainloop smem dead
    {
        s_sq0[tid] = g_sq0[b * SS + mt * 128 + tid];
        s_a0[tid]  = 2.f * m0_[b * SS + mt * 128 + tid];
        s_sq1[tid] = g_sq1[b * SS + nt * 128 + tid];
        s_m1[tid]  = m1_[b * SS + nt * 128 + tid];
    }

    float* Aout  = g_A  + (size_t)b * SS * SS;
    float* Atout = g_At + (size_t)b * SS * SS;

    #pragma unroll 1
    for (int h = 0; h < 2; h++) {
        __syncthreads();
        if (wm == h) {
            #pragma unroll
            for (int mf = 0; mf < 4; mf++) {
                int lr = mf * 16 + g;
                #pragma unroll
                for (int nf = 0; nf < 8; nf++) {
                    int col = wn * 64 + nf * 8 + 2 * t4;
                    *(float2*)&tile[lr * 132 + col] =
                        make_float2(acc[mf][nf][0], acc[mf][nf][1]);
                    *(float2*)&tile[(lr + 8) * 132 + col] =
                        make_float2(acc[mf][nf][2], acc[mf][nf][3]);
                }
            }
        }
        __syncthreads();

        // pass 1: A row-major (64x128), float4 per thread iter
        #pragma unroll
        for (int it = 0; it < 16; it++) {
            int lin = it * 512 + tid * 4;
            int row = lin >> 7, col = lin & 127;
            int grow = h * 64 + row;
            float s0v = s_sq0[grow], a0v = s_a0[grow];
            float4 cr = *(float4*)&tile[row * 132 + col];
            float d2, v0, v1, v2, v3;
            d2 = fmaxf(s0v + s_sq1[col]     - a0v * s_m1[col]     * cr.x, 0.f);
            v0 = rtf32(1.f / (1.f + sqrtf(d2)));
            d2 = fmaxf(s0v + s_sq1[col + 1] - a0v * s_m1[col + 1] * cr.y, 0.f);
            v1 = rtf32(1.f / (1.f + sqrtf(d2)));
            d2 = fmaxf(s0v + s_sq1[col + 2] - a0v * s_m1[col + 2] * cr.z, 0.f);
            v2 = rtf32(1.f / (1.f + sqrtf(d2)));
            d2 = fmaxf(s0v + s_sq1[col + 3] - a0v * s_m1[col + 3] * cr.w, 0.f);
            v3 = rtf32(1.f / (1.f + sqrtf(d2)));
            *(float4*)&Aout[(size_t)(mt * 128 + grow) * SS + nt * 128 + col] =
                make_float4(v0, v1, v2, v3);
        }

        // pass 2: At (transposed), float4 along m
        #pragma unroll
        for (int it = 0; it < 16; it++) {
            int pair = it * 128 + tid;             // 128 cols x 16 rowgroups
            int col = pair >> 4, rg = pair & 15;
            int r0 = rg * 4;
            float s1v = s_sq1[col], m1v = s_m1[col];
            float v[4];
            #pragma unroll
            for (int q = 0; q < 4; q++) {
                int row = r0 + q, grow = h * 64 + row;
                float cr = tile[row * 132 + col];
                float d2 = fmaxf(s_sq0[grow] + s1v - s_a0[grow] * m1v * cr, 0.f);
                v[q] = rtf32(1.f / (1.f + sqrtf(d2)));
            }
            *(float4*)&Atout[(size_t)(nt * 128 + col) * SS + mt * 128 + h * 64 + r0] =
                make_float4(v[0], v[1], v[2], v[3]);
        }
    }
}

// ---------------------------------------------------------------------------
// GEMM B (both aggregations).  blockIdx.y: sel = y>>1 (0:F0a, 1:F1a),
// mt = y&1.  K=256.  Block tile 128x128.
// ---------------------------------------------------------------------------
__global__ __launch_bounds__(128) void gemm_aggr(void)
{
    extern __shared__ char smem[];
    const int tid = threadIdx.x;
    const int wid = tid >> 5, lane = tid & 31;
    const int g = lane >> 2, t4 = lane & 3;
    const int wm = wid & 1, wn = wid >> 1;
    const int b = blockIdx.z, nt = blockIdx.x;
    const int sel = blockIdx.y >> 1;          // 0: F0a, 1: F1a
    const int mt  = blockIdx.y & 1;

    uint32_t sb = smem_u32(smem);
    const float* Ag = (sel ? g_A : g_At) + (size_t)b * SS * SS + (size_t)mt * 128 * SS;
    const float* Bg = (sel ? g_W1t : g_W0t) + (size_t)nt * 128 * SS;

    float acc[4][8][4];
    #pragma unroll
    for (int i = 0; i < 4; i++)
        #pragma unroll
        for (int j = 0; j < 8; j++)
            #pragma unroll
            for (int r = 0; r < 4; r++) acc[i][j][r] = 0.f;

    const uint32_t aoff = (uint32_t)((wm * 64 + g) * 80 + t4 * 4);
    const uint32_t boff = (uint32_t)((wn * 64 + g) * 80 + t4 * 4);

    gemm_mainloop<256>(Ag, Bg, sb, tid, acc, aoff, boff);

    float* O = (sel ? g_F1a : g_F0a) + (size_t)b * SS * DD;
    #pragma unroll
    for (int mf = 0; mf < 4; mf++) {
        int m = mt * 128 + wm * 64 + mf * 16 + g;
        #pragma unroll
        for (int nf = 0; nf < 8; nf++) {
            int col = nt * 128 + wn * 64 + nf * 8 + 2 * t4;
            *(float2*)&O[(size_t)m * DD + col] =
                make_float2(acc[mf][nf][0], acc[mf][nf][1]);
            *(float2*)&O[(size_t)(m + 8) * DD + col] =
                make_float2(acc[mf][nf][2], acc[mf][nf][3]);
        }
    }
}

// ---------------------------------------------------------------------------
// Conv (2ch, h=3, pad 2) + bias + tanh + avgpool(3), float2 per thread,
// 8-row segments.  256 threads cover D=512.
// ---------------------------------------------------------------------------
__device__ __forceinline__ float fast_tanh(float x)
{
    float e = __expf(2.f * x);
    return 1.f - __fdividef(2.f, 1.f + e);
}

__global__ __launch_bounds__(256) void conv_kernel(
    const float* __restrict__ F0r, const float* __restrict__ F1r,
    const float* __restrict__ m0, const float* __restrict__ m1,
    const float* __restrict__ conv_w, const float* __restrict__ conv_b,
    float* __restrict__ out)
{
    const int p = blockIdx.y & 1;
    const int b = blockIdx.y >> 1;
    const float* F  = p ? F1r : F0r;
    const float* mk = p ? m1 : m0;
    const float* Fa = p ? g_F1a : g_F0a;
    float* o = out + ((size_t)p * BB + b) * SS * DD;

    const int s0 = blockIdx.x * 8;
    const int d  = threadIdx.x * 2;

    float w0[3], w1[3];
    #pragma unroll
    for (int h = 0; h < 3; h++) { w0[h] = conv_w[h]; w1[h] = conv_w[3 + h]; }
    const float cb = conv_b[0];

    float2 xf[12], xa[12];
    #pragma unroll
    for (int u = 0; u < 12; u++) {
        int t = s0 - 2 + u;
        bool in = (t >= 0) && (t < SS);
        if (in) {
            float mv = mk[b * SS + t];
            float2 f = *(const float2*)&F[((size_t)b * SS + t) * DD + d];
            xf[u] = make_float2(f.x * mv, f.y * mv);
            xa[u] = *(const float2*)&Fa[((size_t)b * SS + t) * DD + d];
        } else {
            xf[u] = make_float2(0.f, 0.f);
            xa[u] = make_float2(0.f, 0.f);
        }
    }

    float2 y[10];
    #pragma unroll
    for (int u = 0; u < 10; u++) {
        float ax = cb, ay = cb;
        #pragma unroll
        for (int h = 0; h < 3; h++) {
            ax += w0[h] * xf[u + h].x + w1[h] * xa[u + h].x;
            ay += w0[h] * xf[u + h].y + w1[h] * xa[u + h].y;
        }
        y[u] = make_float2(fast_tanh(ax), fast_tanh(ay));
    }
    #pragma unroll
    for (int q = 0; q < 8; q++) {
        float2 r = make_float2(
            (y[q].x + y[q + 1].x + y[q + 2].x) * (1.f / 3.f),
            (y[q].y + y[q + 1].y + y[q + 2].y) * (1.f / 3.f));
        *(float2*)&o[(size_t)(s0 + q) * DD + d] = r;
    }
}

// ---------------------------------------------------------------------------
// Launch
// ---------------------------------------------------------------------------
extern "C" void kernel_launch(void* const* d_in, const int* in_sizes, int n_in,
                              void* d_out, int out_size)
{
    const float* F0r    = (const float*)d_in[0];
    const float* F1r    = (const float*)d_in[1];
    const float* m0     = (const float*)d_in[2];
    const float* m1     = (const float*)d_in[3];
    const float* W0     = (const float*)d_in[4];
    const float* W1     = (const float*)d_in[5];
    const float* conv_w = (const float*)d_in[6];
    const float* conv_b = (const float*)d_in[7];
    float* out = (float*)d_out;

    cudaFuncSetAttribute(gemm_attn, cudaFuncAttributeMaxDynamicSharedMemorySize, GEMM_SMEM);
    cudaFuncSetAttribute(gemm_aggr, cudaFuncAttributeMaxDynamicSharedMemorySize, GEMM_SMEM);

    prep_kernel<<<8448, 256>>>(F0r, F1r, m0, m1, W0, W1);

    gemm_attn<<<dim3(2, 2, BB), 128, GEMM_SMEM>>>(F0r, F1r, m0, m1);
    gemm_aggr<<<dim3(4, 4, BB), 128, GEMM_SMEM>>>();

    conv_kernel<<<dim3(32, 2 * BB), 256>>>(F0r, F1r, m0, m1, conv_w, conv_b, out);
}

// round 11
// speedup vs baseline: 1.3196x; 1.3053x over previous
#include <cuda_runtime.h>
#include <cuda_fp16.h>
#include <cstdint>
#include <math.h>

#define BB 64
#define SS 256
#define DD 512

// ---------------- scratch (__device__ globals; no allocation) ---------------
__device__ __half g_F0h[BB * SS * DD];   // fp16 copies of F0r / F1r
__device__ __half g_F1h[BB * SS * DD];
__device__ __half g_Ah [BB * SS * SS];   // A[b][i][j]  fp16
__device__ __half g_Ath[BB * SS * SS];   // A[b][j][i]  fp16
__device__ __half g_W0th[DD * SS];       // W0^T [d][k] fp16
__device__ __half g_W1th[DD * SS];
__device__ float  g_F0a[BB * SS * DD];
__device__ float  g_F1a[BB * SS * DD];
__device__ float  g_sq0[BB * SS];
__device__ float  g_sq1[BB * SS];

// ---------------- helpers ---------------------------------------------------
__device__ __forceinline__ uint32_t smem_u32(const void* p) {
    uint32_t a;
    asm("{ .reg .u64 t; cvta.to.shared.u64 t, %1; cvt.u32.u64 %0, t; }" : "=r"(a) : "l"(p));
    return a;
}
__device__ __forceinline__ uint32_t lds32(uint32_t a) {
    uint32_t v;
    asm volatile("ld.shared.b32 %0, [%1];" : "=r"(v) : "r"(a));
    return v;
}
#define CP_ASYNC16(dst, src) \
    asm volatile("cp.async.cg.shared.global [%0], [%1], 16;" :: "r"(dst), "l"(src))
#define CP_COMMIT() asm volatile("cp.async.commit_group;" ::: "memory")
#define CP_WAIT1()  asm volatile("cp.async.wait_group 1;" ::: "memory")

// fp16 MMA, fp32 accum: m16n8k16
__device__ __forceinline__ void mma_f16(float* c, const uint32_t* a, const uint32_t* b) {
    asm volatile(
        "mma.sync.aligned.m16n8k16.row.col.f32.f16.f16.f32 "
        "{%0,%1,%2,%3}, {%4,%5,%6,%7}, {%8,%9}, {%0,%1,%2,%3};"
        : "+f"(c[0]), "+f"(c[1]), "+f"(c[2]), "+f"(c[3])
        : "r"(a[0]), "r"(a[1]), "r"(a[2]), "r"(a[3]), "r"(b[0]), "r"(b[1]));
}

// ---------------------------------------------------------------------------
// Prep kernel: sqnorms + fp16 conversion of F (blocks 0..8191, 2 rows each)
//              + W transpose to fp16 (blocks 8192..8447)
// ---------------------------------------------------------------------------
__global__ __launch_bounds__(256) void prep_kernel(
    const float* __restrict__ F0r, const float* __restrict__ F1r,
    const float* __restrict__ m0, const float* __restrict__ m1,
    const float* __restrict__ W0, const float* __restrict__ W1)
{
    __shared__ float sh0[2][4], sh1[2][4];
    __shared__ float t[32][33];
    int bx = blockIdx.x;
    int tid = threadIdx.x;

    if (bx < 8192) {
        int half_ = tid >> 7, lt = tid & 127;
        int row = bx * 2 + half_;
        const float4* r0 = (const float4*)(F0r + (size_t)row * DD);
        const float4* r1 = (const float4*)(F1r + (size_t)row * DD);
        float4 a = r0[lt];
        float4 b = r1[lt];

        // fp16 copies (round-to-nearest)
        {
            size_t base = (size_t)row * DD + lt * 4;
            __half2 p0 = __floats2half2_rn(a.x, a.y);
            __half2 p1 = __floats2half2_rn(a.z, a.w);
            *(__half2*)&g_F0h[base]     = p0;
            *(__half2*)&g_F0h[base + 2] = p1;
            __half2 q0 = __floats2half2_rn(b.x, b.y);
            __half2 q1 = __floats2half2_rn(b.z, b.w);
            *(__half2*)&g_F1h[base]     = q0;
            *(__half2*)&g_F1h[base + 2] = q1;
        }

        float s0 = a.x * a.x + a.y * a.y + a.z * a.z + a.w * a.w;
        float s1 = b.x * b.x + b.y * b.y + b.z * b.z + b.w * b.w;
        #pragma unroll
        for (int o = 16; o > 0; o >>= 1) {
            s0 += __shfl_xor_sync(0xFFFFFFFFu, s0, o);
            s1 += __shfl_xor_sync(0xFFFFFFFFu, s1, o);
        }
        int w = lt >> 5;
        if ((lt & 31) == 0) { sh0[half_][w] = s0; sh1[half_][w] = s1; }
        __syncthreads();
        if (lt == 0) {
            s0 = sh0[half_][0] + sh0[half_][1] + sh0[half_][2] + sh0[half_][3];
            s1 = sh1[half_][0] + sh1[half_][1] + sh1[half_][2] + sh1[half_][3];
            g_sq0[row] = s0 * m0[row];
            g_sq1[row] = s1 * m1[row];
        }
    } else {
        int r = bx - 8192;                 // 0..255
        int sel = r >> 7;
        int d0 = (r & 15) * 32;
        int k0 = ((r >> 4) & 7) * 32;
        const float* W = sel ? W1 : W0;
        __half* Wt = sel ? g_W1th : g_W0th;
        int tx = tid & 31, ty = tid >> 5;  // 32 x 8
        #pragma unroll
        for (int rr = 0; rr < 32; rr += 8)
            t[ty + rr][tx] = W[(size_t)(k0 + ty + rr) * DD + d0 + tx];
        __syncthreads();
        #pragma unroll
        for (int rr = 0; rr < 32; rr += 8)
            Wt[(size_t)(d0 + ty + rr) * SS + k0 + tx] = __float2half_rn(t[tx][ty + rr]);
    }
}

// ---------------------------------------------------------------------------
// fp16 mma.sync GEMM core.  Block tile 128x128, 128 threads, 4 warps in a
// 2x2 grid, warp tile 64x64.  BK=32 halfs (64 B data + 16 B pad = 80 B rows,
// conflict-free).  3-stage cp.async ring, one __syncthreads per k-tile,
// loads 2 tiles ahead.
// ---------------------------------------------------------------------------
#define OPER_BYTES (128 * 80)              // 10240
#define STAGE_BYTES (2 * OPER_BYTES)       // 20480
#define NSTAGE 3
#define GEMM_SMEM (NSTAGE * STAGE_BYTES)   // 61440

template <int KTOT>     // KTOT in halfs
__device__ __forceinline__ void gemm_mainloop(
    const __half* __restrict__ Ag, const __half* __restrict__ Bg,
    uint32_t sb, int tid, float acc[4][8][4],
    uint32_t aoff, uint32_t boff)
{
    constexpr int T = KTOT / 32;

    auto load_tile = [&](int t, int s) {
        uint32_t ab = sb + s * STAGE_BYTES;
        uint32_t bb = ab + OPER_BYTES;
        int k0 = t * 32;
        #pragma unroll
        for (int i = 0; i < 4; i++) {          // 512 chunks each, 4/thread
            int idx = tid + i * 128;
            int row = idx >> 2, part = idx & 3;
            uint32_t doff = (uint32_t)(row * 80 + part * 16);
            CP_ASYNC16(ab + doff, Ag + (size_t)row * KTOT + k0 + part * 8);
            CP_ASYNC16(bb + doff, Bg + (size_t)row * KTOT + k0 + part * 8);
        }
    };

    load_tile(0, 0); CP_COMMIT();
    load_tile(1, 1); CP_COMMIT();

    int s = 0;
    for (int t = 0; t < T; t++) {
        CP_WAIT1();           // tile t resident (t+1 may be in flight)
        __syncthreads();      // visibility; slot s+2 reusable
        int lt = t + 2;
        int ls = s + 2; if (ls >= NSTAGE) ls -= NSTAGE;
        if (lt < T) load_tile(lt, ls);
        CP_COMMIT();

        uint32_t ab = sb + s * STAGE_BYTES + aoff;
        uint32_t bb = sb + s * STAGE_BYTES + OPER_BYTES + boff;
        #pragma unroll
        for (int ks = 0; ks < 2; ks++) {       // two k16 steps (+32 B each)
            uint32_t af[4][4], bf[8][2];
            #pragma unroll
            for (int mf = 0; mf < 4; mf++) {
                uint32_t base = ab + mf * (16 * 80) + ks * 32;
                af[mf][0] = lds32(base);             // A[g][k0..k1]
                af[mf][1] = lds32(base + 8 * 80);    // A[g+8][k0..k1]
                af[mf][2] = lds32(base + 16);        // A[g][k8..k9]
                af[mf][3] = lds32(base + 8 * 80 + 16);
            }
            #pragma unroll
            for (int nf = 0; nf < 8; nf++) {
                uint32_t base = bb + nf * (8 * 80) + ks * 32;
                bf[nf][0] = lds32(base);
                bf[nf][1] = lds32(base + 16);
            }
            #pragma unroll
            for (int mf = 0; mf < 4; mf++)
                #pragma unroll
                for (int nf = 0; nf < 8; nf++)
                    mma_f16(acc[mf][nf], af[mf], bf[nf]);
        }
        if (++s >= NSTAGE) s -= NSTAGE;
    }
}

// ---------------------------------------------------------------------------
// GEMM A (attention): cross tile 128x128 of F0 @ F1^T (K=512) -> g_Ah, g_Ath
// ---------------------------------------------------------------------------
__global__ __launch_bounds__(128) void gemm_attn(
    const float* __restrict__ m0_, const float* __restrict__ m1_)
{
    extern __shared__ char smem[];
    const int tid = threadIdx.x;
    const int wid = tid >> 5, lane = tid & 31;
    const int g = lane >> 2, t4 = lane & 3;
    const int wm = wid & 1, wn = wid >> 1;     // 2 x 2 warp grid
    const int b = blockIdx.z, mt = blockIdx.y, nt = blockIdx.x;

    uint32_t sb = smem_u32(smem);
    const __half* Ag = g_F0h + (size_t)b * SS * DD + (size_t)mt * 128 * DD;
    const __half* Bg = g_F1h + (size_t)b * SS * DD + (size_t)nt * 128 * DD;

    float acc[4][8][4];
    #pragma unroll
    for (int i = 0; i < 4; i++)
        #pragma unroll
        for (int j = 0; j < 8; j++)
            #pragma unroll
            for (int r = 0; r < 4; r++) acc[i][j][r] = 0.f;

    const uint32_t aoff = (uint32_t)((wm * 64 + g) * 80 + t4 * 4);
    const uint32_t boff = (uint32_t)((wn * 64 + g) * 80 + t4 * 4);

    gemm_mainloop<512>(Ag, Bg, sb, tid, acc, aoff, boff);

    // -------------------- attention epilogue (two 64-row halves) ------------
    float* tile = (float*)smem;                         // [64][132] = 33792 B
    float* s_sq0 = (float*)(smem + 33792);              // [128]
    float* s_a0  = s_sq0 + 128;                         // [128] = 2*m0
    float* s_sq1 = s_a0 + 128;                          // [128]
    float* s_m1  = s_sq1 + 128;                         // [128]

    __syncthreads();   // mainloop smem dead
    {
        s_sq0[tid] = g_sq0[b * SS + mt * 128 + tid];
        s_a0[tid]  = 2.f * m0_[b * SS + mt * 128 + tid];
        s_sq1[tid] = g_sq1[b * SS + nt * 128 + tid];
        s_m1[tid]  = m1_[b * SS + nt * 128 + tid];
    }

    __half* Aout  = g_Ah  + (size_t)b * SS * SS;
    __half* Atout = g_Ath + (size_t)b * SS * SS;

    #pragma unroll 1
    for (int h = 0; h < 2; h++) {
        __syncthreads();
        if (wm == h) {
            #pragma unroll
            for (int mf = 0; mf < 4; mf++) {
                int lr = mf * 16 + g;
                #pragma unroll
                for (int nf = 0; nf < 8; nf++) {
                    int col = wn * 64 + nf * 8 + 2 * t4;
                    *(float2*)&tile[lr * 132 + col] =
                        make_float2(acc[mf][nf][0], acc[mf][nf][1]);
                    *(float2*)&tile[(lr + 8) * 132 + col] =
                        make_float2(acc[mf][nf][2], acc[mf][nf][3]);
                }
            }
        }
        __syncthreads();

        // pass 1: A row-major (64x128), 4 cols per thread iter
        #pragma unroll
        for (int it = 0; it < 16; it++) {
            int lin = it * 512 + tid * 4;
            int row = lin >> 7, col = lin & 127;
            int grow = h * 64 + row;
            float s0v = s_sq0[grow], a0v = s_a0[grow];
            float4 cr = *(float4*)&tile[row * 132 + col];
            float d2, v0, v1, v2, v3;
            d2 = fmaxf(s0v + s_sq1[col]     - a0v * s_m1[col]     * cr.x, 0.f);
            v0 = 1.f / (1.f + sqrtf(d2));
            d2 = fmaxf(s0v + s_sq1[col + 1] - a0v * s_m1[col + 1] * cr.y, 0.f);
            v1 = 1.f / (1.f + sqrtf(d2));
            d2 = fmaxf(s0v + s_sq1[col + 2] - a0v * s_m1[col + 2] * cr.z, 0.f);
            v2 = 1.f / (1.f + sqrtf(d2));
            d2 = fmaxf(s0v + s_sq1[col + 3] - a0v * s_m1[col + 3] * cr.w, 0.f);
            v3 = 1.f / (1.f + sqrtf(d2));
            size_t idx = (size_t)(mt * 128 + grow) * SS + nt * 128 + col;
            *(__half2*)&Aout[idx]     = __floats2half2_rn(v0, v1);
            *(__half2*)&Aout[idx + 2] = __floats2half2_rn(v2, v3);
        }

        // pass 2: At (transposed), 4 rows along m per thread iter
        #pragma unroll
        for (int it = 0; it < 16; it++) {
            int pair = it * 128 + tid;             // 128 cols x 16 rowgroups
            int col = pair >> 4, rg = pair & 15;
            int r0 = rg * 4;
            float s1v = s_sq1[col], m1v = s_m1[col];
            float v[4];
            #pragma unroll
            for (int q = 0; q < 4; q++) {
                int row = r0 + q, grow = h * 64 + row;
                float cr = tile[row * 132 + col];
                float d2 = fmaxf(s_sq0[grow] + s1v - s_a0[grow] * m1v * cr, 0.f);
                v[q] = 1.f / (1.f + sqrtf(d2));
            }
            size_t idx = (size_t)(nt * 128 + col) * SS + mt * 128 + h * 64 + r0;
            *(__half2*)&Atout[idx]     = __floats2half2_rn(v[0], v[1]);
            *(__half2*)&Atout[idx + 2] = __floats2half2_rn(v[2], v[3]);
        }
    }
}

// ---------------------------------------------------------------------------
// GEMM B (both aggregations).  blockIdx.y: sel = y>>1 (0:F0a, 1:F1a),
// mt = y&1.  K=256.  Block tile 128x128.
// ---------------------------------------------------------------------------
__global__ __launch_bounds__(128) void gemm_aggr(void)
{
    extern __shared__ char smem[];
    const int tid = threadIdx.x;
    const int wid = tid >> 5, lane = tid & 31;
    const int g = lane >> 2, t4 = lane & 3;
    const int wm = wid & 1, wn = wid >> 1;
    const int b = blockIdx.z, nt = blockIdx.x;
    const int sel = blockIdx.y >> 1;          // 0: F0a, 1: F1a
    const int mt  = blockIdx.y & 1;

    uint32_t sb = smem_u32(smem);
    const __half* Ag = (sel ? g_Ah : g_Ath) + (size_t)b * SS * SS + (size_t)mt * 128 * SS;
    const __half* Bg = (sel ? g_W1th : g_W0th) + (size_t)nt * 128 * SS;

    float acc[4][8][4];
    #pragma unroll
    for (int i = 0; i < 4; i++)
        #pragma unroll
        for (int j = 0; j < 8; j++)
            #pragma unroll
            for (int r = 0; r < 4; r++) acc[i][j][r] = 0.f;

    const uint32_t aoff = (uint32_t)((wm * 64 + g) * 80 + t4 * 4);
    const uint32_t boff = (uint32_t)((wn * 64 + g) * 80 + t4 * 4);

    gemm_mainloop<256>(Ag, Bg, sb, tid, acc, aoff, boff);

    float* O = (sel ? g_F1a : g_F0a) + (size_t)b * SS * DD;
    #pragma unroll
    for (int mf = 0; mf < 4; mf++) {
        int m = mt * 128 + wm * 64 + mf * 16 + g;
        #pragma unroll
        for (int nf = 0; nf < 8; nf++) {
            int col = nt * 128 + wn * 64 + nf * 8 + 2 * t4;
            *(float2*)&O[(size_t)m * DD + col] =
                make_float2(acc[mf][nf][0], acc[mf][nf][1]);
            *(float2*)&O[(size_t)(m + 8) * DD + col] =
                make_float2(acc[mf][nf][2], acc[mf][nf][3]);
        }
    }
}

// ---------------------------------------------------------------------------
// Conv (2ch, h=3, pad 2) + bias + tanh + avgpool(3), float2 per thread,
// 8-row segments.  256 threads cover D=512.
// ---------------------------------------------------------------------------
__device__ __forceinline__ float fast_tanh(float x)
{
    float e = __expf(2.f * x);
    return 1.f - __fdividef(2.f, 1.f + e);
}

__global__ __launch_bounds__(256) void conv_kernel(
    const float* __restrict__ F0r, const float* __restrict__ F1r,
    const float* __restrict__ m0, const float* __restrict__ m1,
    const float* __restrict__ conv_w, const float* __restrict__ conv_b,
    float* __restrict__ out)
{
    const int p = blockIdx.y & 1;
    const int b = blockIdx.y >> 1;
    const float* F  = p ? F1r : F0r;
    const float* mk = p ? m1 : m0;
    const float* Fa = p ? g_F1a : g_F0a;
    float* o = out + ((size_t)p * BB + b) * SS * DD;

    const int s0 = blockIdx.x * 8;
    const int d  = threadIdx.x * 2;

    float w0[3], w1[3];
    #pragma unroll
    for (int h = 0; h < 3; h++) { w0[h] = conv_w[h]; w1[h] = conv_w[3 + h]; }
    const float cb = conv_b[0];

    float2 xf[12], xa[12];
    #pragma unroll
    for (int u = 0; u < 12; u++) {
        int t = s0 - 2 + u;
        bool in = (t >= 0) && (t < SS);
        if (in) {
            float mv = mk[b * SS + t];
            float2 f = *(const float2*)&F[((size_t)b * SS + t) * DD + d];
            xf[u] = make_float2(f.x * mv, f.y * mv);
            xa[u] = *(const float2*)&Fa[((size_t)b * SS + t) * DD + d];
        } else {
            xf[u] = make_float2(0.f, 0.f);
            xa[u] = make_float2(0.f, 0.f);
        }
    }

    float2 y[10];
    #pragma unroll
    for (int u = 0; u < 10; u++) {
        float ax = cb, ay = cb;
        #pragma unroll
        for (int h = 0; h < 3; h++) {
            ax += w0[h] * xf[u + h].x + w1[h] * xa[u + h].x;
            ay += w0[h] * xf[u + h].y + w1[h] * xa[u + h].y;
        }
        y[u] = make_float2(fast_tanh(ax), fast_tanh(ay));
    }
    #pragma unroll
    for (int q = 0; q < 8; q++) {
        float2 r = make_float2(
            (y[q].x + y[q + 1].x + y[q + 2].x) * (1.f / 3.f),
            (y[q].y + y[q + 1].y + y[q + 2].y) * (1.f / 3.f));
        *(float2*)&o[(size_t)(s0 + q) * DD + d] = r;
    }
}

// ---------------------------------------------------------------------------
// Launch
// ---------------------------------------------------------------------------
extern "C" void kernel_launch(void* const* d_in, const int* in_sizes, int n_in,
                              void* d_out, int out_size)
{
    const float* F0r    = (const float*)d_in[0];
    const float* F1r    = (const float*)d_in[1];
    const float* m0     = (const float*)d_in[2];
    const float* m1     = (const float*)d_in[3];
    const float* W0     = (const float*)d_in[4];
    const float* W1     = (const float*)d_in[5];
    const float* conv_w = (const float*)d_in[6];
    const float* conv_b = (const float*)d_in[7];
    float* out = (float*)d_out;

    cudaFuncSetAttribute(gemm_attn, cudaFuncAttributeMaxDynamicSharedMemorySize, GEMM_SMEM);
    cudaFuncSetAttribute(gemm_aggr, cudaFuncAttributeMaxDynamicSharedMemorySize, GEMM_SMEM);

    prep_kernel<<<8448, 256>>>(F0r, F1r, m0, m1, W0, W1);

    gemm_attn<<<dim3(2, 2, BB), 128, GEMM_SMEM>>>(m0, m1);
    gemm_aggr<<<dim3(4, 4, BB), 128, GEMM_SMEM>>>();

    conv_kernel<<<dim3(32, 2 * BB), 256>>>(F0r, F1r, m0, m1, conv_w, conv_b, out);
}

// round 14
// speedup vs baseline: 1.3404x; 1.0158x over previous
#include <cuda_runtime.h>
#include <cuda_fp16.h>
#include <cstdint>
#include <math.h>

#define BB 64
#define SS 256
#define DD 512

// ---------------- scratch (__device__ globals; no allocation) ---------------
__device__ __half g_F0h[BB * SS * DD];   // fp16 copies of F0r / F1r
__device__ __half g_F1h[BB * SS * DD];
__device__ __half g_Ah [BB * SS * SS];   // A[b][i][j]  fp16
__device__ __half g_Ath[BB * SS * SS];   // A[b][j][i]  fp16
__device__ __half g_W0th[DD * SS];       // W0^T [d][k] fp16
__device__ __half g_W1th[DD * SS];
__device__ __half g_F0ah[BB * SS * DD];  // aggregation outputs, fp16
__device__ __half g_F1ah[BB * SS * DD];
__device__ float  g_sq0[BB * SS];
__device__ float  g_sq1[BB * SS];

// ---------------- helpers ---------------------------------------------------
__device__ __forceinline__ uint32_t smem_u32(const void* p) {
    uint32_t a;
    asm("{ .reg .u64 t; cvta.to.shared.u64 t, %1; cvt.u32.u64 %0, t; }" : "=r"(a) : "l"(p));
    return a;
}
__device__ __forceinline__ uint32_t lds32(uint32_t a) {
    uint32_t v;
    asm volatile("ld.shared.b32 %0, [%1];" : "=r"(v) : "r"(a));
    return v;
}
#define CP_ASYNC16(dst, src) \
    asm volatile("cp.async.cg.shared.global [%0], [%1], 16;" :: "r"(dst), "l"(src))
#define CP_COMMIT() asm volatile("cp.async.commit_group;" ::: "memory")
#define CP_WAIT1()  asm volatile("cp.async.wait_group 1;" ::: "memory")

// fp16 MMA, fp32 accum: m16n8k16
__device__ __forceinline__ void mma_f16(float* c, const uint32_t* a, const uint32_t* b) {
    asm volatile(
        "mma.sync.aligned.m16n8k16.row.col.f32.f16.f16.f32 "
        "{%0,%1,%2,%3}, {%4,%5,%6,%7}, {%8,%9}, {%0,%1,%2,%3};"
        : "+f"(c[0]), "+f"(c[1]), "+f"(c[2]), "+f"(c[3])
        : "r"(a[0]), "r"(a[1]), "r"(a[2]), "r"(a[3]), "r"(b[0]), "r"(b[1]));
}

// ---------------------------------------------------------------------------
// Prep kernel: sqnorms + fp16 conversion of F (blocks 0..8191, 2 rows each)
//              + W transpose to fp16 (blocks 8192..8447)
// ---------------------------------------------------------------------------
__global__ __launch_bounds__(256) void prep_kernel(
    const float* __restrict__ F0r, const float* __restrict__ F1r,
    const float* __restrict__ m0, const float* __restrict__ m1,
    const float* __restrict__ W0, const float* __restrict__ W1)
{
    __shared__ float sh0[2][4], sh1[2][4];
    __shared__ float t[32][33];
    int bx = blockIdx.x;
    int tid = threadIdx.x;

    if (bx < 8192) {
        int half_ = tid >> 7, lt = tid & 127;
        int row = bx * 2 + half_;
        const float4* r0 = (const float4*)(F0r + (size_t)row * DD);
        const float4* r1 = (const float4*)(F1r + (size_t)row * DD);
        float4 a = r0[lt];
        float4 b = r1[lt];

        // fp16 copies (round-to-nearest)
        {
            size_t base = (size_t)row * DD + lt * 4;
            *(__half2*)&g_F0h[base]     = __floats2half2_rn(a.x, a.y);
            *(__half2*)&g_F0h[base + 2] = __floats2half2_rn(a.z, a.w);
            *(__half2*)&g_F1h[base]     = __floats2half2_rn(b.x, b.y);
            *(__half2*)&g_F1h[base + 2] = __floats2half2_rn(b.z, b.w);
        }

        float s0 = a.x * a.x + a.y * a.y + a.z * a.z + a.w * a.w;
        float s1 = b.x * b.x + b.y * b.y + b.z * b.z + b.w * b.w;
        #pragma unroll
        for (int o = 16; o > 0; o >>= 1) {
            s0 += __shfl_xor_sync(0xFFFFFFFFu, s0, o);
            s1 += __shfl_xor_sync(0xFFFFFFFFu, s1, o);
        }
        int w = lt >> 5;
        if ((lt & 31) == 0) { sh0[half_][w] = s0; sh1[half_][w] = s1; }
        __syncthreads();
        if (lt == 0) {
            s0 = sh0[half_][0] + sh0[half_][1] + sh0[half_][2] + sh0[half_][3];
            s1 = sh1[half_][0] + sh1[half_][1] + sh1[half_][2] + sh1[half_][3];
            g_sq0[row] = s0 * m0[row];
            g_sq1[row] = s1 * m1[row];
        }
    } else {
        int r = bx - 8192;                 // 0..255
        int sel = r >> 7;
        int d0 = (r & 15) * 32;
        int k0 = ((r >> 4) & 7) * 32;
        const float* W = sel ? W1 : W0;
        __half* Wt = sel ? g_W1th : g_W0th;
        int tx = tid & 31, ty = tid >> 5;  // 32 x 8
        #pragma unroll
        for (int rr = 0; rr < 32; rr += 8)
            t[ty + rr][tx] = W[(size_t)(k0 + ty + rr) * DD + d0 + tx];
        __syncthreads();
        #pragma unroll
        for (int rr = 0; rr < 32; rr += 8)
            Wt[(size_t)(d0 + ty + rr) * SS + k0 + tx] = __float2half_rn(t[tx][ty + rr]);
    }
}

// ---------------------------------------------------------------------------
// fp16 mma.sync GEMM core.  Block tile 128x128, 128 threads, 4 warps in a
// 2x2 grid, warp tile 64x64.  BK=32 halfs (64 B data + 16 B pad = 80 B rows,
// conflict-free).  3-stage cp.async ring, one __syncthreads per k-tile,
// loads 2 tiles ahead.
// ---------------------------------------------------------------------------
#define OPER_BYTES (128 * 80)              // 10240
#define STAGE_BYTES (2 * OPER_BYTES)       // 20480
#define NSTAGE 3
#define GEMM_SMEM (NSTAGE * STAGE_BYTES)   // 61440

template <int KTOT>     // KTOT in halfs
__device__ __forceinline__ void gemm_mainloop(
    const __half* __restrict__ Ag, const __half* __restrict__ Bg,
    uint32_t sb, int tid, float acc[4][8][4],
    uint32_t aoff, uint32_t boff)
{
    constexpr int T = KTOT / 32;

    auto load_tile = [&](int t, int s) {
        uint32_t ab = sb + s * STAGE_BYTES;
        uint32_t bb = ab + OPER_BYTES;
        int k0 = t * 32;
        #pragma unroll
        for (int i = 0; i < 4; i++) {          // 512 chunks each, 4/thread
            int idx = tid + i * 128;
            int row = idx >> 2, part = idx & 3;
            uint32_t doff = (uint32_t)(row * 80 + part * 16);
            CP_ASYNC16(ab + doff, Ag + (size_t)row * KTOT + k0 + part * 8);
            CP_ASYNC16(bb + doff, Bg + (size_t)row * KTOT + k0 + part * 8);
        }
    };

    load_tile(0, 0); CP_COMMIT();
    load_tile(1, 1); CP_COMMIT();

    int s = 0;
    for (int t = 0; t < T; t++) {
        CP_WAIT1();           // tile t resident (t+1 may be in flight)
        __syncthreads();      // visibility; slot s+2 reusable
        int lt = t + 2;
        int ls = s + 2; if (ls >= NSTAGE) ls -= NSTAGE;
        if (lt < T) load_tile(lt, ls);
        CP_COMMIT();

        uint32_t ab = sb + s * STAGE_BYTES + aoff;
        uint32_t bb = sb + s * STAGE_BYTES + OPER_BYTES + boff;
        #pragma unroll
        for (int ks = 0; ks < 2; ks++) {       // two k16 steps (+32 B each)
            uint32_t af[4][4], bf[8][2];
            #pragma unroll
            for (int mf = 0; mf < 4; mf++) {
                uint32_t base = ab + mf * (16 * 80) + ks * 32;
                af[mf][0] = lds32(base);
                af[mf][1] = lds32(base + 8 * 80);
                af[mf][2] = lds32(base + 16);
                af[mf][3] = lds32(base + 8 * 80 + 16);
            }
            #pragma unroll
            for (int nf = 0; nf < 8; nf++) {
                uint32_t base = bb + nf * (8 * 80) + ks * 32;
                bf[nf][0] = lds32(base);
                bf[nf][1] = lds32(base + 16);
            }
            #pragma unroll
            for (int mf = 0; mf < 4; mf++)
                #pragma unroll
                for (int nf = 0; nf < 8; nf++)
                    mma_f16(acc[mf][nf], af[mf], bf[nf]);
        }
        if (++s >= NSTAGE) s -= NSTAGE;
    }
}

// ---------------------------------------------------------------------------
// GEMM A (attention): cross tile 128x128 of F0 @ F1^T (K=512) -> g_Ah, g_Ath
// ---------------------------------------------------------------------------
__global__ __launch_bounds__(128) void gemm_attn(
    const float* __restrict__ m0_, const float* __restrict__ m1_)
{
    extern __shared__ char smem[];
    const int tid = threadIdx.x;
    const int wid = tid >> 5, lane = tid & 31;
    const int g = lane >> 2, t4 = lane & 3;
    const int wm = wid & 1, wn = wid >> 1;     // 2 x 2 warp grid
    const int b = blockIdx.z, mt = blockIdx.y, nt = blockIdx.x;

    uint32_t sb = smem_u32(smem);
    const __half* Ag = g_F0h + (size_t)b * SS * DD + (size_t)mt * 128 * DD;
    const __half* Bg = g_F1h + (size_t)b * SS * DD + (size_t)nt * 128 * DD;

    float acc[4][8][4];
    #pragma unroll
    for (int i = 0; i < 4; i++)
        #pragma unroll
        for (int j = 0; j < 8; j++)
            #pragma unroll
            for (int r = 0; r < 4; r++) acc[i][j][r] = 0.f;

    const uint32_t aoff = (uint32_t)((wm * 64 + g) * 80 + t4 * 4);
    const uint32_t boff = (uint32_t)((wn * 64 + g) * 80 + t4 * 4);

    gemm_mainloop<512>(Ag, Bg, sb, tid, acc, aoff, boff);

    // -------------------- attention epilogue (two 64-row halves) ------------
    float* tile = (float*)smem;                         // [64][132] = 33792 B
    float* s_sq0 = (float*)(smem + 33792);              // [128]
    float* s_a0  = s_sq0 + 128;                         // [128] = 2*m0
    float* s_sq1 = s_a0 + 128;                          // [128]
    float* s_m1  = s_sq1 + 128;                         // [128]

    __syncthreads();   // mainloop smem dead
    {
        s_sq0[tid] = g_sq0[b * SS + mt * 128 + tid];
        s_a0[tid]  = 2.f * m0_[b * SS + mt * 128 + tid];
        s_sq1[tid] = g_sq1[b * SS + nt * 128 + tid];
        s_m1[tid]  = m1_[b * SS + nt * 128 + tid];
    }

    __half* Aout  = g_Ah  + (size_t)b * SS * SS;
    __half* Atout = g_Ath + (size_t)b * SS * SS;

    #pragma unroll 1
    for (int h = 0; h < 2; h++) {
        __syncthreads();
        if (wm == h) {
            #pragma unroll
            for (int mf = 0; mf < 4; mf++) {
                int lr = mf * 16 + g;
                #pragma unroll
                for (int nf = 0; nf < 8; nf++) {
                    int col = wn * 64 + nf * 8 + 2 * t4;
                    *(float2*)&tile[lr * 132 + col] =
                        make_float2(acc[mf][nf][0], acc[mf][nf][1]);
                    *(float2*)&tile[(lr + 8) * 132 + col] =
                        make_float2(acc[mf][nf][2], acc[mf][nf][3]);
                }
            }
        }
        __syncthreads();

        // pass 1: A row-major (64x128), 4 cols per thread iter
        #pragma unroll
        for (int it = 0; it < 16; it++) {
            int lin = it * 512 + tid * 4;
            int row = lin >> 7, col = lin & 127;
            int grow = h * 64 + row;
            float s0v = s_sq0[grow], a0v = s_a0[grow];
            float4 cr = *(float4*)&tile[row * 132 + col];
            float d2, v0, v1, v2, v3;
            d2 = fmaxf(s0v + s_sq1[col]     - a0v * s_m1[col]     * cr.x, 0.f);
            v0 = 1.f / (1.f + sqrtf(d2));
            d2 = fmaxf(s0v + s_sq1[col + 1] - a0v * s_m1[col + 1] * cr.y, 0.f);
            v1 = 1.f / (1.f + sqrtf(d2));
            d2 = fmaxf(s0v + s_sq1[col + 2] - a0v * s_m1[col + 2] * cr.z, 0.f);
            v2 = 1.f / (1.f + sqrtf(d2));
            d2 = fmaxf(s0v + s_sq1[col + 3] - a0v * s_m1[col + 3] * cr.w, 0.f);
            v3 = 1.f / (1.f + sqrtf(d2));
            size_t idx = (size_t)(mt * 128 + grow) * SS + nt * 128 + col;
            *(__half2*)&Aout[idx]     = __floats2half2_rn(v0, v1);
            *(__half2*)&Aout[idx + 2] = __floats2half2_rn(v2, v3);
        }

        // pass 2: At (transposed), 4 rows along m per thread iter
        #pragma unroll
        for (int it = 0; it < 16; it++) {
            int pair = it * 128 + tid;             // 128 cols x 16 rowgroups
            int col = pair >> 4, rg = pair & 15;
            int r0 = rg * 4;
            float s1v = s_sq1[col], m1v = s_m1[col];
            float v[4];
            #pragma unroll
            for (int q = 0; q < 4; q++) {
                int row = r0 + q, grow = h * 64 + row;
                float cr = tile[row * 132 + col];
                float d2 = fmaxf(s_sq0[grow] + s1v - s_a0[grow] * m1v * cr, 0.f);
                v[q] = 1.f / (1.f + sqrtf(d2));
            }
            size_t idx = (size_t)(nt * 128 + col) * SS + mt * 128 + h * 64 + r0;
            *(__half2*)&Atout[idx]     = __floats2half2_rn(v[0], v[1]);
            *(__half2*)&Atout[idx + 2] = __floats2half2_rn(v[2], v[3]);
        }
    }
}

// ---------------------------------------------------------------------------
// GEMM B (both aggregations).  blockIdx.y: sel = y>>1 (0:F0a, 1:F1a),
// mt = y&1.  K=256.  Block tile 128x128.  Output fp16.
// ---------------------------------------------------------------------------
__global__ __launch_bounds__(128) void gemm_aggr(void)
{
    extern __shared__ char smem[];
    const int tid = threadIdx.x;
    const int wid = tid >> 5, lane = tid & 31;
    const int g = lane >> 2, t4 = lane & 3;
    const int wm = wid & 1, wn = wid >> 1;
    const int b = blockIdx.z, nt = blockIdx.x;
    const int sel = blockIdx.y >> 1;          // 0: F0a, 1: F1a
    const int mt  = blockIdx.y & 1;

    uint32_t sb = smem_u32(smem);
    const __half* Ag = (sel ? g_Ah : g_Ath) + (size_t)b * SS * SS + (size_t)mt * 128 * SS;
    const __half* Bg = (sel ? g_W1th : g_W0th) + (size_t)nt * 128 * SS;

    float acc[4][8][4];
    #pragma unroll
    for (int i = 0; i < 4; i++)
        #pragma unroll
        for (int j = 0; j < 8; j++)
            #pragma unroll
            for (int r = 0; r < 4; r++) acc[i][j][r] = 0.f;

    const uint32_t aoff = (uint32_t)((wm * 64 + g) * 80 + t4 * 4);
    const uint32_t boff = (uint32_t)((wn * 64 + g) * 80 + t4 * 4);

    gemm_mainloop<256>(Ag, Bg, sb, tid, acc, aoff, boff);

    __half* O = (sel ? g_F1ah : g_F0ah) + (size_t)b * SS * DD;
    #pragma unroll
    for (int mf = 0; mf < 4; mf++) {
        int m = mt * 128 + wm * 64 + mf * 16 + g;
        #pragma unroll
        for (int nf = 0; nf < 8; nf++) {
            int col = nt * 128 + wn * 64 + nf * 8 + 2 * t4;
            *(__half2*)&O[(size_t)m * DD + col] =
                __floats2half2_rn(acc[mf][nf][0], acc[mf][nf][1]);
            *(__half2*)&O[(size_t)(m + 8) * DD + col] =
                __floats2half2_rn(acc[mf][nf][2], acc[mf][nf][3]);
        }
    }
}

// ---------------------------------------------------------------------------
// Conv (2ch, h=3, pad 2) + bias + tanh + avgpool(3), fp16 inputs, fp32 out.
// 2 d-columns per thread (one __half2 load per row per array), 8-row segs.
// ---------------------------------------------------------------------------
__device__ __forceinline__ float fast_tanh(float x)
{
    float e = __expf(2.f * x);
    return 1.f - __fdividef(2.f, 1.f + e);
}

__global__ __launch_bounds__(256) void conv_kernel(
    const float* __restrict__ m0, const float* __restrict__ m1,
    const float* __restrict__ conv_w, const float* __restrict__ conv_b,
    float* __restrict__ out)
{
    const int p = blockIdx.y & 1;
    const int b = blockIdx.y >> 1;
    const __half* F  = p ? g_F1h : g_F0h;
    const float* mk  = p ? m1 : m0;
    const __half* Fa = p ? g_F1ah : g_F0ah;
    float* o = out + ((size_t)p * BB + b) * SS * DD;

    const int s0 = blockIdx.x * 8;
    const int d  = threadIdx.x * 2;

    float w0[3], w1[3];
    #pragma unroll
    for (int h = 0; h < 3; h++) { w0[h] = conv_w[h]; w1[h] = conv_w[3 + h]; }
    const float cb = conv_b[0];

    float2 xf[12], xa[12];
    #pragma unroll
    for (int u = 0; u < 12; u++) {
        int t = s0 - 2 + u;
        bool in = (t >= 0) && (t < SS);
        if (in) {
            float mv = mk[b * SS + t];
            float2 f = __half22float2(*(const __half2*)&F[((size_t)b * SS + t) * DD + d]);
            xf[u] = make_float2(f.x * mv, f.y * mv);
            xa[u] = __half22float2(*(const __half2*)&Fa[((size_t)b * SS + t) * DD + d]);
        } else {
            xf[u] = make_float2(0.f, 0.f);
            xa[u] = make_float2(0.f, 0.f);
        }
    }

    float2 y[10];
    #pragma unroll
    for (int u = 0; u < 10; u++) {
        float ax = cb, ay = cb;
        #pragma unroll
        for (int h = 0; h < 3; h++) {
            ax += w0[h] * xf[u + h].x + w1[h] * xa[u + h].x;
            ay += w0[h] * xf[u + h].y + w1[h] * xa[u + h].y;
        }
        y[u] = make_float2(fast_tanh(ax), fast_tanh(ay));
    }
    #pragma unroll
    for (int q = 0; q < 8; q++) {
        float2 r = make_float2(
            (y[q].x + y[q + 1].x + y[q + 2].x) * (1.f / 3.f),
            (y[q].y + y[q + 1].y + y[q + 2].y) * (1.f / 3.f));
        *(float2*)&o[(size_t)(s0 + q) * DD + d] = r;
    }
}

// ---------------------------------------------------------------------------
// Launch
// ---------------------------------------------------------------------------
extern "C" void kernel_launch(void* const* d_in, const int* in_sizes, int n_in,
                              void* d_out, int out_size)
{
    const float* F0r    = (const float*)d_in[0];
    const float* F1r    = (const float*)d_in[1];
    const float* m0     = (const float*)d_in[2];
    const float* m1     = (const float*)d_in[3];
    const float* W0     = (const float*)d_in[4];
    const float* W1     = (const float*)d_in[5];
    const float* conv_w = (const float*)d_in[6];
    const float* conv_b = (const float*)d_in[7];
    float* out = (float*)d_out;

    cudaFuncSetAttribute(gemm_attn, cudaFuncAttributeMaxDynamicSharedMemorySize, GEMM_SMEM);
    cudaFuncSetAttribute(gemm_aggr, cudaFuncAttributeMaxDynamicSharedMemorySize, GEMM_SMEM);

    prep_kernel<<<8448, 256>>>(F0r, F1r, m0, m1, W0, W1);

    gemm_attn<<<dim3(2, 2, BB), 128, GEMM_SMEM>>>(m0, m1);
    gemm_aggr<<<dim3(4, 4, BB), 128, GEMM_SMEM>>>();

    conv_kernel<<<dim3(32, 2 * BB), 256>>>(m0, m1, conv_w, conv_b, out);
}

// round 15
// speedup vs baseline: 1.4226x; 1.0613x over previous
#include <cuda_runtime.h>
#include <cuda_fp16.h>
#include <cstdint>
#include <math.h>

#define BB 64
#define SS 256
#define DD 512

// ---------------- scratch (__device__ globals; no allocation) ---------------
__device__ __half g_F0h[BB * SS * DD];   // fp16 MASKED copies of F0r / F1r
__device__ __half g_F1h[BB * SS * DD];
__device__ __half g_Ah [BB * SS * SS];   // A[b][i][j]  fp16
__device__ __half g_Ath[BB * SS * SS];   // A[b][j][i]  fp16
__device__ __half g_W0th[DD * SS];       // W0^T [d][k] fp16
__device__ __half g_W1th[DD * SS];
__device__ __half g_F0ah[BB * SS * DD];  // aggregation outputs, fp16
__device__ __half g_F1ah[BB * SS * DD];
__device__ float  g_sq0[BB * SS];
__device__ float  g_sq1[BB * SS];

// ---------------- helpers ---------------------------------------------------
__device__ __forceinline__ uint32_t smem_u32(const void* p) {
    uint32_t a;
    asm("{ .reg .u64 t; cvta.to.shared.u64 t, %1; cvt.u32.u64 %0, t; }" : "=r"(a) : "l"(p));
    return a;
}
__device__ __forceinline__ uint32_t lds32(uint32_t a) {
    uint32_t v;
    asm volatile("ld.shared.b32 %0, [%1];" : "=r"(v) : "r"(a));
    return v;
}
#define CP_ASYNC16(dst, src) \
    asm volatile("cp.async.cg.shared.global [%0], [%1], 16;" :: "r"(dst), "l"(src))
#define CP_COMMIT() asm volatile("cp.async.commit_group;" ::: "memory")
#define CP_WAIT1()  asm volatile("cp.async.wait_group 1;" ::: "memory")

// fp16 MMA, fp32 accum: m16n8k16
__device__ __forceinline__ void mma_f16(float* c, const uint32_t* a, const uint32_t* b) {
    asm volatile(
        "mma.sync.aligned.m16n8k16.row.col.f32.f16.f16.f32 "
        "{%0,%1,%2,%3}, {%4,%5,%6,%7}, {%8,%9}, {%0,%1,%2,%3};"
        : "+f"(c[0]), "+f"(c[1]), "+f"(c[2]), "+f"(c[3])
        : "r"(a[0]), "r"(a[1]), "r"(a[2]), "r"(a[3]), "r"(b[0]), "r"(b[1]));
}

__device__ __forceinline__ float tanh_fast(float x) {
    float y;
    asm("tanh.approx.f32 %0, %1;" : "=f"(y) : "f"(x));
    return y;
}

// ---------------------------------------------------------------------------
// Prep kernel: sqnorms + MASKED fp16 conversion of F (blocks 0..8191, 2 rows)
//              + W transpose to fp16 (blocks 8192..8447)
// ---------------------------------------------------------------------------
__global__ __launch_bounds__(256) void prep_kernel(
    const float* __restrict__ F0r, const float* __restrict__ F1r,
    const float* __restrict__ m0, const float* __restrict__ m1,
    const float* __restrict__ W0, const float* __restrict__ W1)
{
    __shared__ float sh0[2][4], sh1[2][4];
    __shared__ float t[32][33];
    int bx = blockIdx.x;
    int tid = threadIdx.x;

    if (bx < 8192) {
        int half_ = tid >> 7, lt = tid & 127;
        int row = bx * 2 + half_;
        const float4* r0 = (const float4*)(F0r + (size_t)row * DD);
        const float4* r1 = (const float4*)(F1r + (size_t)row * DD);
        float4 a = r0[lt];
        float4 b = r1[lt];
        float mv0 = m0[row], mv1 = m1[row];

        // masked fp16 copies (round-to-nearest)
        {
            size_t base = (size_t)row * DD + lt * 4;
            *(__half2*)&g_F0h[base]     = __floats2half2_rn(a.x * mv0, a.y * mv0);
            *(__half2*)&g_F0h[base + 2] = __floats2half2_rn(a.z * mv0, a.w * mv0);
            *(__half2*)&g_F1h[base]     = __floats2half2_rn(b.x * mv1, b.y * mv1);
            *(__half2*)&g_F1h[base + 2] = __floats2half2_rn(b.z * mv1, b.w * mv1);
        }

        float s0 = a.x * a.x + a.y * a.y + a.z * a.z + a.w * a.w;
        float s1 = b.x * b.x + b.y * b.y + b.z * b.z + b.w * b.w;
        #pragma unroll
        for (int o = 16; o > 0; o >>= 1) {
            s0 += __shfl_xor_sync(0xFFFFFFFFu, s0, o);
            s1 += __shfl_xor_sync(0xFFFFFFFFu, s1, o);
        }
        int w = lt >> 5;
        if ((lt & 31) == 0) { sh0[half_][w] = s0; sh1[half_][w] = s1; }
        __syncthreads();
        if (lt == 0) {
            s0 = sh0[half_][0] + sh0[half_][1] + sh0[half_][2] + sh0[half_][3];
            s1 = sh1[half_][0] + sh1[half_][1] + sh1[half_][2] + sh1[half_][3];
            g_sq0[row] = s0 * mv0;
            g_sq1[row] = s1 * mv1;
        }
    } else {
        int r = bx - 8192;                 // 0..255
        int sel = r >> 7;
        int d0 = (r & 15) * 32;
        int k0 = ((r >> 4) & 7) * 32;
        const float* W = sel ? W1 : W0;
        __half* Wt = sel ? g_W1th : g_W0th;
        int tx = tid & 31, ty = tid >> 5;  // 32 x 8
        #pragma unroll
        for (int rr = 0; rr < 32; rr += 8)
            t[ty + rr][tx] = W[(size_t)(k0 + ty + rr) * DD + d0 + tx];
        __syncthreads();
        #pragma unroll
        for (int rr = 0; rr < 32; rr += 8)
            Wt[(size_t)(d0 + ty + rr) * SS + k0 + tx] = __float2half_rn(t[tx][ty + rr]);
    }
}

// ---------------------------------------------------------------------------
// fp16 mma.sync GEMM core.  Block tile 128x128, 128 threads, 4 warps in a
// 2x2 grid, warp tile 64x64.  BK=32 halfs (64 B data + 16 B pad = 80 B rows,
// conflict-free).  3-stage cp.async ring, one __syncthreads per k-tile,
// loads 2 tiles ahead.
// ---------------------------------------------------------------------------
#define OPER_BYTES (128 * 80)              // 10240
#define STAGE_BYTES (2 * OPER_BYTES)       // 20480
#define NSTAGE 3
#define GEMM_SMEM (NSTAGE * STAGE_BYTES)   // 61440

template <int KTOT>     // KTOT in halfs
__device__ __forceinline__ void gemm_mainloop(
    const __half* __restrict__ Ag, const __half* __restrict__ Bg,
    uint32_t sb, int tid, float acc[4][8][4],
    uint32_t aoff, uint32_t boff)
{
    constexpr int T = KTOT / 32;

    auto load_tile = [&](int t, int s) {
        uint32_t ab = sb + s * STAGE_BYTES;
        uint32_t bb = ab + OPER_BYTES;
        int k0 = t * 32;
        #pragma unroll
        for (int i = 0; i < 4; i++) {          // 512 chunks each, 4/thread
            int idx = tid + i * 128;
            int row = idx >> 2, part = idx & 3;
            uint32_t doff = (uint32_t)(row * 80 + part * 16);
            CP_ASYNC16(ab + doff, Ag + (size_t)row * KTOT + k0 + part * 8);
            CP_ASYNC16(bb + doff, Bg + (size_t)row * KTOT + k0 + part * 8);
        }
    };

    load_tile(0, 0); CP_COMMIT();
    load_tile(1, 1); CP_COMMIT();

    int s = 0;
    for (int t = 0; t < T; t++) {
        CP_WAIT1();           // tile t resident (t+1 may be in flight)
        __syncthreads();      // visibility; slot s+2 reusable
        int lt = t + 2;
        int ls = s + 2; if (ls >= NSTAGE) ls -= NSTAGE;
        if (lt < T) load_tile(lt, ls);
        CP_COMMIT();

        uint32_t ab = sb + s * STAGE_BYTES + aoff;
        uint32_t bb = sb + s * STAGE_BYTES + OPER_BYTES + boff;
        #pragma unroll
        for (int ks = 0; ks < 2; ks++) {       // two k16 steps (+32 B each)
            uint32_t af[4][4], bf[8][2];
            #pragma unroll
            for (int mf = 0; mf < 4; mf++) {
                uint32_t base = ab + mf * (16 * 80) + ks * 32;
                af[mf][0] = lds32(base);
                af[mf][1] = lds32(base + 8 * 80);
                af[mf][2] = lds32(base + 16);
                af[mf][3] = lds32(base + 8 * 80 + 16);
            }
            #pragma unroll
            for (int nf = 0; nf < 8; nf++) {
                uint32_t base = bb + nf * (8 * 80) + ks * 32;
                bf[nf][0] = lds32(base);
                bf[nf][1] = lds32(base + 16);
            }
            #pragma unroll
            for (int mf = 0; mf < 4; mf++)
                #pragma unroll
                for (int nf = 0; nf < 8; nf++)
                    mma_f16(acc[mf][nf], af[mf], bf[nf]);
        }
        if (++s >= NSTAGE) s -= NSTAGE;
    }
}

// ---------------------------------------------------------------------------
// GEMM A (attention): cross tile 128x128 of masked F0 @ F1^T (K=512)
// -> A = 1/(1+sqrt(max(sq0+sq1-2*cross,0))) -> g_Ah, g_Ath
// ---------------------------------------------------------------------------
__global__ __launch_bounds__(128) void gemm_attn(void)
{
    extern __shared__ char smem[];
    const int tid = threadIdx.x;
    const int wid = tid >> 5, lane = tid & 31;
    const int g = lane >> 2, t4 = lane & 3;
    const int wm = wid & 1, wn = wid >> 1;     // 2 x 2 warp grid
    const int b = blockIdx.z, mt = blockIdx.y, nt = blockIdx.x;

    uint32_t sb = smem_u32(smem);
    const __half* Ag = g_F0h + (size_t)b * SS * DD + (size_t)mt * 128 * DD;
    const __half* Bg = g_F1h + (size_t)b * SS * DD + (size_t)nt * 128 * DD;

    float acc[4][8][4];
    #pragma unroll
    for (int i = 0; i < 4; i++)
        #pragma unroll
        for (int j = 0; j < 8; j++)
            #pragma unroll
            for (int r = 0; r < 4; r++) acc[i][j][r] = 0.f;

    const uint32_t aoff = (uint32_t)((wm * 64 + g) * 80 + t4 * 4);
    const uint32_t boff = (uint32_t)((wn * 64 + g) * 80 + t4 * 4);

    gemm_mainloop<512>(Ag, Bg, sb, tid, acc, aoff, boff);

    // -------------------- attention epilogue (two 64-row halves) ------------
    float* tile = (float*)smem;                         // [64][132] = 33792 B
    float* s_sq0 = (float*)(smem + 33792);              // [128]
    float* s_sq1 = s_sq0 + 128;                         // [128]

    __syncthreads();   // mainloop smem dead
    {
        s_sq0[tid] = g_sq0[b * SS + mt * 128 + tid];
        s_sq1[tid] = g_sq1[b * SS + nt * 128 + tid];
    }

    __half* Aout  = g_Ah  + (size_t)b * SS * SS;
    __half* Atout = g_Ath + (size_t)b * SS * SS;

    #pragma unroll 1
    for (int h = 0; h < 2; h++) {
        __syncthreads();
        if (wm == h) {
            #pragma unroll
            for (int mf = 0; mf < 4; mf++) {
                int lr = mf * 16 + g;
                #pragma unroll
                for (int nf = 0; nf < 8; nf++) {
                    int col = wn * 64 + nf * 8 + 2 * t4;
                    *(float2*)&tile[lr * 132 + col] =
                        make_float2(acc[mf][nf][0], acc[mf][nf][1]);
                    *(float2*)&tile[(lr + 8) * 132 + col] =
                        make_float2(acc[mf][nf][2], acc[mf][nf][3]);
                }
            }
        }
        __syncthreads();

        // pass 1: A row-major (64x128), 4 cols per thread iter
        #pragma unroll
        for (int it = 0; it < 16; it++) {
            int lin = it * 512 + tid * 4;
            int row = lin >> 7, col = lin & 127;
            int grow = h * 64 + row;
            float s0v = s_sq0[grow];
            float4 cr = *(float4*)&tile[row * 132 + col];
            float d2, v0, v1, v2, v3;
            d2 = fmaxf(s0v + s_sq1[col]     - 2.f * cr.x, 0.f);
            v0 = 1.f / (1.f + sqrtf(d2));
            d2 = fmaxf(s0v + s_sq1[col + 1] - 2.f * cr.y, 0.f);
            v1 = 1.f / (1.f + sqrtf(d2));
            d2 = fmaxf(s0v + s_sq1[col + 2] - 2.f * cr.z, 0.f);
            v2 = 1.f / (1.f + sqrtf(d2));
            d2 = fmaxf(s0v + s_sq1[col + 3] - 2.f * cr.w, 0.f);
            v3 = 1.f / (1.f + sqrtf(d2));
            size_t idx = (size_t)(mt * 128 + grow) * SS + nt * 128 + col;
            *(__half2*)&Aout[idx]     = __floats2half2_rn(v0, v1);
            *(__half2*)&Aout[idx + 2] = __floats2half2_rn(v2, v3);
        }

        // pass 2: At (transposed), 4 rows along m per thread iter
        #pragma unroll
        for (int it = 0; it < 16; it++) {
            int pair = it * 128 + tid;             // 128 cols x 16 rowgroups
            int col = pair >> 4, rg = pair & 15;
            int r0 = rg * 4;
            float s1v = s_sq1[col];
            float v[4];
            #pragma unroll
            for (int q = 0; q < 4; q++) {
                int row = r0 + q, grow = h * 64 + row;
                float cr = tile[row * 132 + col];
                float d2 = fmaxf(s_sq0[grow] + s1v - 2.f * cr, 0.f);
                v[q] = 1.f / (1.f + sqrtf(d2));
            }
            size_t idx = (size_t)(nt * 128 + col) * SS + mt * 128 + h * 64 + r0;
            *(__half2*)&Atout[idx]     = __floats2half2_rn(v[0], v[1]);
            *(__half2*)&Atout[idx + 2] = __floats2half2_rn(v[2], v[3]);
        }
    }
}

// ---------------------------------------------------------------------------
// GEMM B (both aggregations).  blockIdx.y: sel = y>>1 (0:F0a, 1:F1a),
// mt = y&1.  K=256.  Block tile 128x128.  Output fp16.
// ---------------------------------------------------------------------------
__global__ __launch_bounds__(128) void gemm_aggr(void)
{
    extern __shared__ char smem[];
    const int tid = threadIdx.x;
    const int wid = tid >> 5, lane = tid & 31;
    const int g = lane >> 2, t4 = lane & 3;
    const int wm = wid & 1, wn = wid >> 1;
    const int b = blockIdx.z, nt = blockIdx.x;
    const int sel = blockIdx.y >> 1;          // 0: F0a, 1: F1a
    const int mt  = blockIdx.y & 1;

    uint32_t sb = smem_u32(smem);
    const __half* Ag = (sel ? g_Ah : g_Ath) + (size_t)b * SS * SS + (size_t)mt * 128 * SS;
    const __half* Bg = (sel ? g_W1th : g_W0th) + (size_t)nt * 128 * SS;

    float acc[4][8][4];
    #pragma unroll
    for (int i = 0; i < 4; i++)
        #pragma unroll
        for (int j = 0; j < 8; j++)
            #pragma unroll
            for (int r = 0; r < 4; r++) acc[i][j][r] = 0.f;

    const uint32_t aoff = (uint32_t)((wm * 64 + g) * 80 + t4 * 4);
    const uint32_t boff = (uint32_t)((wn * 64 + g) * 80 + t4 * 4);

    gemm_mainloop<256>(Ag, Bg, sb, tid, acc, aoff, boff);

    __half* O = (sel ? g_F1ah : g_F0ah) + (size_t)b * SS * DD;
    #pragma unroll
    for (int mf = 0; mf < 4; mf++) {
        int m = mt * 128 + wm * 64 + mf * 16 + g;
        #pragma unroll
        for (int nf = 0; nf < 8; nf++) {
            int col = nt * 128 + wn * 64 + nf * 8 + 2 * t4;
            *(__half2*)&O[(size_t)m * DD + col] =
                __floats2half2_rn(acc[mf][nf][0], acc[mf][nf][1]);
            *(__half2*)&O[(size_t)(m + 8) * DD + col] =
                __floats2half2_rn(acc[mf][nf][2], acc[mf][nf][3]);
        }
    }
}

// ---------------------------------------------------------------------------
// Conv (2ch, h=3, pad 2) + bias + tanh.approx + avgpool(3), fp16 inputs
// (pre-masked), fp32 out.  2 d-columns per thread, 8-row segments.
// ---------------------------------------------------------------------------
__global__ __launch_bounds__(256) void conv_kernel(
    const float* __restrict__ conv_w, const float* __restrict__ conv_b,
    float* __restrict__ out)
{
    const int p = blockIdx.y & 1;
    const int b = blockIdx.y >> 1;
    const __half* F  = p ? g_F1h : g_F0h;
    const __half* Fa = p ? g_F1ah : g_F0ah;
    float* o = out + ((size_t)p * BB + b) * SS * DD;

    const int s0 = blockIdx.x * 8;
    const int d  = threadIdx.x * 2;

    float w0[3], w1[3];
    #pragma unroll
    for (int h = 0; h < 3; h++) { w0[h] = conv_w[h]; w1[h] = conv_w[3 + h]; }
    const float cb = conv_b[0];

    float2 xf[12], xa[12];
    #pragma unroll
    for (int u = 0; u < 12; u++) {
        int t = s0 - 2 + u;
        bool in = (t >= 0) && (t < SS);
        if (in) {
            xf[u] = __half22float2(*(const __half2*)&F[((size_t)b * SS + t) * DD + d]);
            xa[u] = __half22float2(*(const __half2*)&Fa[((size_t)b * SS + t) * DD + d]);
        } else {
            xf[u] = make_float2(0.f, 0.f);
            xa[u] = make_float2(0.f, 0.f);
        }
    }

    float2 y[10];
    #pragma unroll
    for (int u = 0; u < 10; u++) {
        float ax = cb, ay = cb;
        #pragma unroll
        for (int h = 0; h < 3; h++) {
            ax += w0[h] * xf[u + h].x + w1[h] * xa[u + h].x;
            ay += w0[h] * xf[u + h].y + w1[h] * xa[u + h].y;
        }
        y[u] = make_float2(tanh_fast(ax), tanh_fast(ay));
    }
    #pragma unroll
    for (int q = 0; q < 8; q++) {
        float2 r = make_float2(
            (y[q].x + y[q + 1].x + y[q + 2].x) * (1.f / 3.f),
            (y[q].y + y[q + 1].y + y[q + 2].y) * (1.f / 3.f));
        *(float2*)&o[(size_t)(s0 + q) * DD + d] = r;
    }
}

// ---------------------------------------------------------------------------
// Launch
// ---------------------------------------------------------------------------
extern "C" void kernel_launch(void* const* d_in, const int* in_sizes, int n_in,
                              void* d_out, int out_size)
{
    const float* F0r    = (const float*)d_in[0];
    const float* F1r    = (const float*)d_in[1];
    const float* m0     = (const float*)d_in[2];
    const float* m1     = (const float*)d_in[3];
    const float* W0     = (const float*)d_in[4];
    const float* W1     = (const float*)d_in[5];
    const float* conv_w = (const float*)d_in[6];
    const float* conv_b = (const float*)d_in[7];
    float* out = (float*)d_out;

    cudaFuncSetAttribute(gemm_attn, cudaFuncAttributeMaxDynamicSharedMemorySize, GEMM_SMEM);
    cudaFuncSetAttribute(gemm_aggr, cudaFuncAttributeMaxDynamicSharedMemorySize, GEMM_SMEM);

    prep_kernel<<<8448, 256>>>(F0r, F1r, m0, m1, W0, W1);

    gemm_attn<<<dim3(2, 2, BB), 128, GEMM_SMEM>>>();
    gemm_aggr<<<dim3(4, 4, BB), 128, GEMM_SMEM>>>();

    conv_kernel<<<dim3(32, 2 * BB), 256>>>(conv_w, conv_b, out);
}

// round 16
// speedup vs baseline: 1.4747x; 1.0366x over previous
#include <cuda_runtime.h>
#include <cuda_fp16.h>
#include <cstdint>
#include <math.h>

#define BB 64
#define SS 256
#define DD 512

// ---------------- scratch (__device__ globals; no allocation) ---------------
__device__ __half g_F0h[BB * SS * DD];   // fp16 MASKED copies of F0r / F1r
__device__ __half g_F1h[BB * SS * DD];
__device__ __half g_Ah [BB * SS * SS];   // A[b][i][j]  fp16
__device__ __half g_Ath[BB * SS * SS];   // A[b][j][i]  fp16
__device__ __half g_W0th[DD * SS];       // W0^T [d][k] fp16
__device__ __half g_W1th[DD * SS];
__device__ __half g_F0ah[BB * SS * DD];  // aggregation outputs, fp16
__device__ __half g_F1ah[BB * SS * DD];
__device__ float  g_sq0[BB * SS];
__device__ float  g_sq1[BB * SS];

// ---------------- helpers ---------------------------------------------------
__device__ __forceinline__ uint32_t smem_u32(const void* p) {
    uint32_t a;
    asm("{ .reg .u64 t; cvta.to.shared.u64 t, %1; cvt.u32.u64 %0, t; }" : "=r"(a) : "l"(p));
    return a;
}
__device__ __forceinline__ uint32_t lds32(uint32_t a) {
    uint32_t v;
    asm volatile("ld.shared.b32 %0, [%1];" : "=r"(v) : "r"(a));
    return v;
}
#define CP_ASYNC16(dst, src) \
    asm volatile("cp.async.cg.shared.global [%0], [%1], 16;" :: "r"(dst), "l"(src))
#define CP_COMMIT() asm volatile("cp.async.commit_group;" ::: "memory")
#define CP_WAIT1()  asm volatile("cp.async.wait_group 1;" ::: "memory")

// fp16 MMA, fp32 accum: m16n8k16
__device__ __forceinline__ void mma_f16(float* c, const uint32_t* a, const uint32_t* b) {
    asm volatile(
        "mma.sync.aligned.m16n8k16.row.col.f32.f16.f16.f32 "
        "{%0,%1,%2,%3}, {%4,%5,%6,%7}, {%8,%9}, {%0,%1,%2,%3};"
        : "+f"(c[0]), "+f"(c[1]), "+f"(c[2]), "+f"(c[3])
        : "r"(a[0]), "r"(a[1]), "r"(a[2]), "r"(a[3]), "r"(b[0]), "r"(b[1]));
}

__device__ __forceinline__ float tanh_fast(float x) {
    float y;
    asm("tanh.approx.f32 %0, %1;" : "=f"(y) : "f"(x));
    return y;
}

// ---------------------------------------------------------------------------
// Prep kernel: sqnorms + MASKED fp16 conversion of F (blocks 0..8191, 2 rows)
//              + W transpose to fp16 (blocks 8192..8447)
// ---------------------------------------------------------------------------
__global__ __launch_bounds__(256) void prep_kernel(
    const float* __restrict__ F0r, const float* __restrict__ F1r,
    const float* __restrict__ m0, const float* __restrict__ m1,
    const float* __restrict__ W0, const float* __restrict__ W1)
{
    __shared__ float sh0[2][4], sh1[2][4];
    __shared__ float t[32][33];
    int bx = blockIdx.x;
    int tid = threadIdx.x;

    if (bx < 8192) {
        int half_ = tid >> 7, lt = tid & 127;
        int row = bx * 2 + half_;
        const float4* r0 = (const float4*)(F0r + (size_t)row * DD);
        const float4* r1 = (const float4*)(F1r + (size_t)row * DD);
        float4 a = r0[lt];
        float4 b = r1[lt];
        float mv0 = m0[row], mv1 = m1[row];

        // masked fp16 copies (round-to-nearest)
        {
            size_t base = (size_t)row * DD + lt * 4;
            *(__half2*)&g_F0h[base]     = __floats2half2_rn(a.x * mv0, a.y * mv0);
            *(__half2*)&g_F0h[base + 2] = __floats2half2_rn(a.z * mv0, a.w * mv0);
            *(__half2*)&g_F1h[base]     = __floats2half2_rn(b.x * mv1, b.y * mv1);
            *(__half2*)&g_F1h[base + 2] = __floats2half2_rn(b.z * mv1, b.w * mv1);
        }

        float s0 = a.x * a.x + a.y * a.y + a.z * a.z + a.w * a.w;
        float s1 = b.x * b.x + b.y * b.y + b.z * b.z + b.w * b.w;
        #pragma unroll
        for (int o = 16; o > 0; o >>= 1) {
            s0 += __shfl_xor_sync(0xFFFFFFFFu, s0, o);
            s1 += __shfl_xor_sync(0xFFFFFFFFu, s1, o);
        }
        int w = lt >> 5;
        if ((lt & 31) == 0) { sh0[half_][w] = s0; sh1[half_][w] = s1; }
        __syncthreads();
        if (lt == 0) {
            s0 = sh0[half_][0] + sh0[half_][1] + sh0[half_][2] + sh0[half_][3];
            s1 = sh1[half_][0] + sh1[half_][1] + sh1[half_][2] + sh1[half_][3];
            g_sq0[row] = s0 * mv0;
            g_sq1[row] = s1 * mv1;
        }
    } else {
        int r = bx - 8192;                 // 0..255
        int sel = r >> 7;
        int d0 = (r & 15) * 32;
        int k0 = ((r >> 4) & 7) * 32;
        const float* W = sel ? W1 : W0;
        __half* Wt = sel ? g_W1th : g_W0th;
        int tx = tid & 31, ty = tid >> 5;  // 32 x 8
        #pragma unroll
        for (int rr = 0; rr < 32; rr += 8)
            t[ty + rr][tx] = W[(size_t)(k0 + ty + rr) * DD + d0 + tx];
        __syncthreads();
        #pragma unroll
        for (int rr = 0; rr < 32; rr += 8)
            Wt[(size_t)(d0 + ty + rr) * SS + k0 + tx] = __float2half_rn(t[tx][ty + rr]);
    }
}

// ---------------------------------------------------------------------------
// fp16 mma.sync GEMM core.  Block tile 128x128, 128 threads, 4 warps in a
// 2x2 grid, warp tile 64x64.  BK=32 halfs (64 B data + 16 B pad = 80 B rows,
// conflict-free).  3-stage cp.async ring, one __syncthreads per k-tile,
// loads 2 tiles ahead.
// ---------------------------------------------------------------------------
#define OPER_BYTES (128 * 80)              // 10240
#define STAGE_BYTES (2 * OPER_BYTES)       // 20480
#define NSTAGE 3
#define GEMM_SMEM (NSTAGE * STAGE_BYTES)   // 61440

template <int KTOT>     // KTOT in halfs
__device__ __forceinline__ void gemm_mainloop(
    const __half* __restrict__ Ag, const __half* __restrict__ Bg,
    uint32_t sb, int tid, float acc[4][8][4],
    uint32_t aoff, uint32_t boff)
{
    constexpr int T = KTOT / 32;

    auto load_tile = [&](int t, int s) {
        uint32_t ab = sb + s * STAGE_BYTES;
        uint32_t bb = ab + OPER_BYTES;
        int k0 = t * 32;
        #pragma unroll
        for (int i = 0; i < 4; i++) {          // 512 chunks each, 4/thread
            int idx = tid + i * 128;
            int row = idx >> 2, part = idx & 3;
            uint32_t doff = (uint32_t)(row * 80 + part * 16);
            CP_ASYNC16(ab + doff, Ag + (size_t)row * KTOT + k0 + part * 8);
            CP_ASYNC16(bb + doff, Bg + (size_t)row * KTOT + k0 + part * 8);
        }
    };

    load_tile(0, 0); CP_COMMIT();
    load_tile(1, 1); CP_COMMIT();

    int s = 0;
    for (int t = 0; t < T; t++) {
        CP_WAIT1();           // tile t resident (t+1 may be in flight)
        __syncthreads();      // visibility; slot s+2 reusable
        int lt = t + 2;
        int ls = s + 2; if (ls >= NSTAGE) ls -= NSTAGE;
        if (lt < T) load_tile(lt, ls);
        CP_COMMIT();

        uint32_t ab = sb + s * STAGE_BYTES + aoff;
        uint32_t bb = sb + s * STAGE_BYTES + OPER_BYTES + boff;
        #pragma unroll
        for (int ks = 0; ks < 2; ks++) {       // two k16 steps (+32 B each)
            uint32_t af[4][4], bf[8][2];
            #pragma unroll
            for (int mf = 0; mf < 4; mf++) {
                uint32_t base = ab + mf * (16 * 80) + ks * 32;
                af[mf][0] = lds32(base);
                af[mf][1] = lds32(base + 8 * 80);
                af[mf][2] = lds32(base + 16);
                af[mf][3] = lds32(base + 8 * 80 + 16);
            }
            #pragma unroll
            for (int nf = 0; nf < 8; nf++) {
                uint32_t base = bb + nf * (8 * 80) + ks * 32;
                bf[nf][0] = lds32(base);
                bf[nf][1] = lds32(base + 16);
            }
            #pragma unroll
            for (int mf = 0; mf < 4; mf++)
                #pragma unroll
                for (int nf = 0; nf < 8; nf++)
                    mma_f16(acc[mf][nf], af[mf], bf[nf]);
        }
        if (++s >= NSTAGE) s -= NSTAGE;
    }
}

// ---------------------------------------------------------------------------
// GEMM A (attention): cross tile 128x128 of masked F0 @ F1^T (K=512)
// -> A = 1/(1+sqrt(max(sq0+sq1-2*cross,0))) -> g_Ah, g_Ath
// ---------------------------------------------------------------------------
__global__ __launch_bounds__(128) void gemm_attn(void)
{
    extern __shared__ char smem[];
    const int tid = threadIdx.x;
    const int wid = tid >> 5, lane = tid & 31;
    const int g = lane >> 2, t4 = lane & 3;
    const int wm = wid & 1, wn = wid >> 1;     // 2 x 2 warp grid
    const int b = blockIdx.z, mt = blockIdx.y, nt = blockIdx.x;

    uint32_t sb = smem_u32(smem);
    const __half* Ag = g_F0h + (size_t)b * SS * DD + (size_t)mt * 128 * DD;
    const __half* Bg = g_F1h + (size_t)b * SS * DD + (size_t)nt * 128 * DD;

    float acc[4][8][4];
    #pragma unroll
    for (int i = 0; i < 4; i++)
        #pragma unroll
        for (int j = 0; j < 8; j++)
            #pragma unroll
            for (int r = 0; r < 4; r++) acc[i][j][r] = 0.f;

    const uint32_t aoff = (uint32_t)((wm * 64 + g) * 80 + t4 * 4);
    const uint32_t boff = (uint32_t)((wn * 64 + g) * 80 + t4 * 4);

    gemm_mainloop<512>(Ag, Bg, sb, tid, acc, aoff, boff);

    // -------------------- attention epilogue (two 64-row halves) ------------
    float* tile = (float*)smem;                         // [64][132] = 33792 B
    float* s_sq0 = (float*)(smem + 33792);              // [128]
    float* s_sq1 = s_sq0 + 128;                         // [128]

    __syncthreads();   // mainloop smem dead
    {
        s_sq0[tid] = g_sq0[b * SS + mt * 128 + tid];
        s_sq1[tid] = g_sq1[b * SS + nt * 128 + tid];
    }

    __half* Aout  = g_Ah  + (size_t)b * SS * SS;
    __half* Atout = g_Ath + (size_t)b * SS * SS;

    #pragma unroll 1
    for (int h = 0; h < 2; h++) {
        __syncthreads();
        if (wm == h) {
            #pragma unroll
            for (int mf = 0; mf < 4; mf++) {
                int lr = mf * 16 + g;
                #pragma unroll
                for (int nf = 0; nf < 8; nf++) {
                    int col = wn * 64 + nf * 8 + 2 * t4;
                    *(float2*)&tile[lr * 132 + col] =
                        make_float2(acc[mf][nf][0], acc[mf][nf][1]);
                    *(float2*)&tile[(lr + 8) * 132 + col] =
                        make_float2(acc[mf][nf][2], acc[mf][nf][3]);
                }
            }
        }
        __syncthreads();

        // pass 1: A row-major (64x128), 4 cols per thread iter
        #pragma unroll
        for (int it = 0; it < 16; it++) {
            int lin = it * 512 + tid * 4;
            int row = lin >> 7, col = lin & 127;
            int grow = h * 64 + row;
            float s0v = s_sq0[grow];
            float4 cr = *(float4*)&tile[row * 132 + col];
            float d2, v0, v1, v2, v3;
            d2 = fmaxf(s0v + s_sq1[col]     - 2.f * cr.x, 0.f);
            v0 = 1.f / (1.f + sqrtf(d2));
            d2 = fmaxf(s0v + s_sq1[col + 1] - 2.f * cr.y, 0.f);
            v1 = 1.f / (1.f + sqrtf(d2));
            d2 = fmaxf(s0v + s_sq1[col + 2] - 2.f * cr.z, 0.f);
            v2 = 1.f / (1.f + sqrtf(d2));
            d2 = fmaxf(s0v + s_sq1[col + 3] - 2.f * cr.w, 0.f);
            v3 = 1.f / (1.f + sqrtf(d2));
            size_t idx = (size_t)(mt * 128 + grow) * SS + nt * 128 + col;
            *(__half2*)&Aout[idx]     = __floats2half2_rn(v0, v1);
            *(__half2*)&Aout[idx + 2] = __floats2half2_rn(v2, v3);
        }

        // pass 2: At (transposed), 4 rows along m per thread iter
        #pragma unroll
        for (int it = 0; it < 16; it++) {
            int pair = it * 128 + tid;             // 128 cols x 16 rowgroups
            int col = pair >> 4, rg = pair & 15;
            int r0 = rg * 4;
            float s1v = s_sq1[col];
            float v[4];
            #pragma unroll
            for (int q = 0; q < 4; q++) {
                int row = r0 + q, grow = h * 64 + row;
                float cr = tile[row * 132 + col];
                float d2 = fmaxf(s_sq0[grow] + s1v - 2.f * cr, 0.f);
                v[q] = 1.f / (1.f + sqrtf(d2));
            }
            size_t idx = (size_t)(nt * 128 + col) * SS + mt * 128 + h * 64 + r0;
            *(__half2*)&Atout[idx]     = __floats2half2_rn(v[0], v[1]);
            *(__half2*)&Atout[idx + 2] = __floats2half2_rn(v[2], v[3]);
        }
    }
}

// ---------------------------------------------------------------------------
// GEMM B (both aggregations).  blockIdx.y: sel = y>>1 (0:F0a, 1:F1a),
// mt = y&1.  K=256.  Block tile 128x128.  Output fp16.
// ---------------------------------------------------------------------------
__global__ __launch_bounds__(128) void gemm_aggr(void)
{
    extern __shared__ char smem[];
    const int tid = threadIdx.x;
    const int wid = tid >> 5, lane = tid & 31;
    const int g = lane >> 2, t4 = lane & 3;
    const int wm = wid & 1, wn = wid >> 1;
    const int b = blockIdx.z, nt = blockIdx.x;
    const int sel = blockIdx.y >> 1;          // 0: F0a, 1: F1a
    const int mt  = blockIdx.y & 1;

    uint32_t sb = smem_u32(smem);
    const __half* Ag = (sel ? g_Ah : g_Ath) + (size_t)b * SS * SS + (size_t)mt * 128 * SS;
    const __half* Bg = (sel ? g_W1th : g_W0th) + (size_t)nt * 128 * SS;

    float acc[4][8][4];
    #pragma unroll
    for (int i = 0; i < 4; i++)
        #pragma unroll
        for (int j = 0; j < 8; j++)
            #pragma unroll
            for (int r = 0; r < 4; r++) acc[i][j][r] = 0.f;

    const uint32_t aoff = (uint32_t)((wm * 64 + g) * 80 + t4 * 4);
    const uint32_t boff = (uint32_t)((wn * 64 + g) * 80 + t4 * 4);

    gemm_mainloop<256>(Ag, Bg, sb, tid, acc, aoff, boff);

    __half* O = (sel ? g_F1ah : g_F0ah) + (size_t)b * SS * DD;
    #pragma unroll
    for (int mf = 0; mf < 4; mf++) {
        int m = mt * 128 + wm * 64 + mf * 16 + g;
        #pragma unroll
        for (int nf = 0; nf < 8; nf++) {
            int col = nt * 128 + wn * 64 + nf * 8 + 2 * t4;
            *(__half2*)&O[(size_t)m * DD + col] =
                __floats2half2_rn(acc[mf][nf][0], acc[mf][nf][1]);
            *(__half2*)&O[(size_t)(m + 8) * DD + col] =
                __floats2half2_rn(acc[mf][nf][2], acc[mf][nf][3]);
        }
    }
}

// ---------------------------------------------------------------------------
// Conv (2ch, h=3, pad 2) + bias + tanh.approx + avgpool(3), fp16 inputs
// (pre-masked), fp32 out.  Rolling-window: 128 threads x 4 columns, 8-row
// segments, 2-register rings for stencil and pool partials.  Interior blocks
// take an unpredicated fast path.
// ---------------------------------------------------------------------------
template <bool SAFE>
__device__ __forceinline__ void conv_body(
    const __half* __restrict__ F, const __half* __restrict__ Fa,
    float* __restrict__ o, int s0,
    float w00, float w01, float w02,
    float w10, float w11, float w12, float cb)
{
    float4 aA = make_float4(0.f, 0.f, 0.f, 0.f);   // y[t-2] partial (h0,h1 taps)
    float4 aB = make_float4(0.f, 0.f, 0.f, 0.f);   // y[t-1] partial (h0 tap)
    float4 pA = make_float4(0.f, 0.f, 0.f, 0.f);   // out[u-2] partial (2 y's)
    float4 pB = make_float4(0.f, 0.f, 0.f, 0.f);   // out[u-1] partial (1 y)

    #pragma unroll
    for (int t = 0; t < 12; t++) {
        int s = s0 - 2 + t;
        float4 xf = make_float4(0.f, 0.f, 0.f, 0.f);
        float4 xa = make_float4(0.f, 0.f, 0.f, 0.f);
        if (SAFE || ((unsigned)s < (unsigned)SS)) {
            uint2 rf = *(const uint2*)(F  + (size_t)s * DD);
            uint2 ra = *(const uint2*)(Fa + (size_t)s * DD);
            float2 f0 = __half22float2(*(__half2*)&rf.x);
            float2 f1 = __half22float2(*(__half2*)&rf.y);
            float2 g0 = __half22float2(*(__half2*)&ra.x);
            float2 g1 = __half22float2(*(__half2*)&ra.y);
            xf = make_float4(f0.x, f0.y, f1.x, f1.y);
            xa = make_float4(g0.x, g0.y, g1.x, g1.y);
        }

        if (t >= 2) {
            // complete y[t-2] with h=2 tap
            float4 y;
            y.x = tanh_fast(aA.x + w02 * xf.x + w12 * xa.x);
            y.y = tanh_fast(aA.y + w02 * xf.y + w12 * xa.y);
            y.z = tanh_fast(aA.z + w02 * xf.z + w12 * xa.z);
            y.w = tanh_fast(aA.w + w02 * xf.w + w12 * xa.w);
            if (t >= 4) {
                float4 r;
                r.x = (pA.x + y.x) * (1.f / 3.f);
                r.y = (pA.y + y.y) * (1.f / 3.f);
                r.z = (pA.z + y.z) * (1.f / 3.f);
                r.w = (pA.w + y.w) * (1.f / 3.f);
                *(float4*)(o + (size_t)(s0 + t - 4) * DD) = r;
            }
            pA.x = pB.x + y.x; pA.y = pB.y + y.y;
            pA.z = pB.z + y.z; pA.w = pB.w + y.w;
            pB = y;
        }
        // rotate stencil partials
        float4 nA, nB;
        nA.x = aB.x + w01 * xf.x + w11 * xa.x;
        nA.y = aB.y + w01 * xf.y + w11 * xa.y;
        nA.z = aB.z + w01 * xf.z + w11 * xa.z;
        nA.w = aB.w + w01 * xf.w + w11 * xa.w;
        nB.x = cb + w00 * xf.x + w10 * xa.x;
        nB.y = cb + w00 * xf.y + w10 * xa.y;
        nB.z = cb + w00 * xf.z + w10 * xa.z;
        nB.w = cb + w00 * xf.w + w10 * xa.w;
        aA = nA; aB = nB;
    }
}

__global__ __launch_bounds__(128) void conv_kernel(
    const float* __restrict__ conv_w, const float* __restrict__ conv_b,
    float* __restrict__ out)
{
    const int p = blockIdx.y & 1;
    const int b = blockIdx.y >> 1;
    const int dof = threadIdx.x * 4;
    const __half* F  = (p ? g_F1h : g_F0h) + (size_t)b * SS * DD + dof;
    const __half* Fa = (p ? g_F1ah : g_F0ah) + (size_t)b * SS * DD + dof;
    float* o = out + ((size_t)p * BB + b) * SS * DD + dof;
    const int s0 = blockIdx.x * 8;

    float w00 = conv_w[0], w01 = conv_w[1], w02 = conv_w[2];
    float w10 = conv_w[3], w11 = conv_w[4], w12 = conv_w[5];
    float cb  = conv_b[0];

    if (s0 >= 2 && s0 + 9 < SS)
        conv_body<true >(F, Fa, o, s0, w00, w01, w02, w10, w11, w12, cb);
    else
        conv_body<false>(F, Fa, o, s0, w00, w01, w02, w10, w11, w12, cb);
}

// ---------------------------------------------------------------------------
// Launch
// ---------------------------------------------------------------------------
extern "C" void kernel_launch(void* const* d_in, const int* in_sizes, int n_in,
                              void* d_out, int out_size)
{
    const float* F0r    = (const float*)d_in[0];
    const float* F1r    = (const float*)d_in[1];
    const float* m0     = (const float*)d_in[2];
    const float* m1     = (const float*)d_in[3];
    const float* W0     = (const float*)d_in[4];
    const float* W1     = (const float*)d_in[5];
    const float* conv_w = (const float*)d_in[6];
    const float* conv_b = (const float*)d_in[7];
    float* out = (float*)d_out;

    cudaFuncSetAttribute(gemm_attn, cudaFuncAttributeMaxDynamicSharedMemorySize, GEMM_SMEM);
    cudaFuncSetAttribute(gemm_aggr, cudaFuncAttributeMaxDynamicSharedMemorySize, GEMM_SMEM);

    prep_kernel<<<8448, 256>>>(F0r, F1r, m0, m1, W0, W1);

    gemm_attn<<<dim3(2, 2, BB), 128, GEMM_SMEM>>>();
    gemm_aggr<<<dim3(4, 4, BB), 128, GEMM_SMEM>>>();

    conv_kernel<<<dim3(32, 2 * BB), 128>>>(conv_w, conv_b, out);
}

// round 17
// speedup vs baseline: 1.4920x; 1.0117x over previous
#include <cuda_runtime.h>
#include <cuda_fp16.h>
#include <cstdint>
#include <math.h>

#define BB 64
#define SS 256
#define DD 512

// ---------------- scratch (__device__ globals; no allocation) ---------------
__device__ __half g_F0h[BB * SS * DD];   // fp16 MASKED copies of F0r / F1r
__device__ __half g_F1h[BB * SS * DD];
__device__ __half g_Ah [BB * SS * SS];   // A[b][i][j]  fp16
__device__ __half g_Ath[BB * SS * SS];   // A[b][j][i]  fp16
__device__ __half g_W0th[DD * SS];       // W0^T [d][k] fp16
__device__ __half g_W1th[DD * SS];
__device__ __half g_F0ah[BB * SS * DD];  // Fa boundary rows only (for conv_edge)
__device__ __half g_F1ah[BB * SS * DD];
__device__ float  g_sq0[BB * SS];
__device__ float  g_sq1[BB * SS];

// ---------------- helpers ---------------------------------------------------
__device__ __forceinline__ uint32_t smem_u32(const void* p) {
    uint32_t a;
    asm("{ .reg .u64 t; cvta.to.shared.u64 t, %1; cvt.u32.u64 %0, t; }" : "=r"(a) : "l"(p));
    return a;
}
__device__ __forceinline__ uint32_t lds32(uint32_t a) {
    uint32_t v;
    asm volatile("ld.shared.b32 %0, [%1];" : "=r"(v) : "r"(a));
    return v;
}
#define CP_ASYNC16(dst, src) \
    asm volatile("cp.async.cg.shared.global [%0], [%1], 16;" :: "r"(dst), "l"(src))
#define CP_COMMIT() asm volatile("cp.async.commit_group;" ::: "memory")
#define CP_WAIT1()  asm volatile("cp.async.wait_group 1;" ::: "memory")

// fp16 MMA, fp32 accum: m16n8k16
__device__ __forceinline__ void mma_f16(float* c, const uint32_t* a, const uint32_t* b) {
    asm volatile(
        "mma.sync.aligned.m16n8k16.row.col.f32.f16.f16.f32 "
        "{%0,%1,%2,%3}, {%4,%5,%6,%7}, {%8,%9}, {%0,%1,%2,%3};"
        : "+f"(c[0]), "+f"(c[1]), "+f"(c[2]), "+f"(c[3])
        : "r"(a[0]), "r"(a[1]), "r"(a[2]), "r"(a[3]), "r"(b[0]), "r"(b[1]));
}

__device__ __forceinline__ float tanh_fast(float x) {
    float y;
    asm("tanh.approx.f32 %0, %1;" : "=f"(y) : "f"(x));
    return y;
}

// ---------------------------------------------------------------------------
// Prep kernel: sqnorms + MASKED fp16 conversion of F (blocks 0..8191, 2 rows)
//              + W transpose to fp16 (blocks 8192..8447)
// ---------------------------------------------------------------------------
__global__ __launch_bounds__(256) void prep_kernel(
    const float* __restrict__ F0r, const float* __restrict__ F1r,
    const float* __restrict__ m0, const float* __restrict__ m1,
    const float* __restrict__ W0, const float* __restrict__ W1)
{
    __shared__ float sh0[2][4], sh1[2][4];
    __shared__ float t[32][33];
    int bx = blockIdx.x;
    int tid = threadIdx.x;

    if (bx < 8192) {
        int half_ = tid >> 7, lt = tid & 127;
        int row = bx * 2 + half_;
        const float4* r0 = (const float4*)(F0r + (size_t)row * DD);
        const float4* r1 = (const float4*)(F1r + (size_t)row * DD);
        float4 a = r0[lt];
        float4 b = r1[lt];
        float mv0 = m0[row], mv1 = m1[row];

        {
            size_t base = (size_t)row * DD + lt * 4;
            *(__half2*)&g_F0h[base]     = __floats2half2_rn(a.x * mv0, a.y * mv0);
            *(__half2*)&g_F0h[base + 2] = __floats2half2_rn(a.z * mv0, a.w * mv0);
            *(__half2*)&g_F1h[base]     = __floats2half2_rn(b.x * mv1, b.y * mv1);
            *(__half2*)&g_F1h[base + 2] = __floats2half2_rn(b.z * mv1, b.w * mv1);
        }

        float s0 = a.x * a.x + a.y * a.y + a.z * a.z + a.w * a.w;
        float s1 = b.x * b.x + b.y * b.y + b.z * b.z + b.w * b.w;
        #pragma unroll
        for (int o = 16; o > 0; o >>= 1) {
            s0 += __shfl_xor_sync(0xFFFFFFFFu, s0, o);
            s1 += __shfl_xor_sync(0xFFFFFFFFu, s1, o);
        }
        int w = lt >> 5;
        if ((lt & 31) == 0) { sh0[half_][w] = s0; sh1[half_][w] = s1; }
        __syncthreads();
        if (lt == 0) {
            s0 = sh0[half_][0] + sh0[half_][1] + sh0[half_][2] + sh0[half_][3];
            s1 = sh1[half_][0] + sh1[half_][1] + sh1[half_][2] + sh1[half_][3];
            g_sq0[row] = s0 * mv0;
            g_sq1[row] = s1 * mv1;
        }
    } else {
        int r = bx - 8192;                 // 0..255
        int sel = r >> 7;
        int d0 = (r & 15) * 32;
        int k0 = ((r >> 4) & 7) * 32;
        const float* W = sel ? W1 : W0;
        __half* Wt = sel ? g_W1th : g_W0th;
        int tx = tid & 31, ty = tid >> 5;  // 32 x 8
        #pragma unroll
        for (int rr = 0; rr < 32; rr += 8)
            t[ty + rr][tx] = W[(size_t)(k0 + ty + rr) * DD + d0 + tx];
        __syncthreads();
        #pragma unroll
        for (int rr = 0; rr < 32; rr += 8)
            Wt[(size_t)(d0 + ty + rr) * SS + k0 + tx] = __float2half_rn(t[tx][ty + rr]);
    }
}

// ---------------------------------------------------------------------------
// fp16 mma.sync GEMM core.  Block tile 128x128, 128 threads, 4 warps in a
// 2x2 grid, warp tile 64x64.  BK=32 halfs (64 B data + 16 B pad = 80 B rows,
// conflict-free).  3-stage cp.async ring, one __syncthreads per k-tile,
// loads 2 tiles ahead.
// ---------------------------------------------------------------------------
#define OPER_BYTES (128 * 80)              // 10240
#define STAGE_BYTES (2 * OPER_BYTES)       // 20480
#define NSTAGE 3
#define GEMM_SMEM (NSTAGE * STAGE_BYTES)   // 61440

template <int KTOT>     // KTOT in halfs
__device__ __forceinline__ void gemm_mainloop(
    const __half* __restrict__ Ag, const __half* __restrict__ Bg,
    uint32_t sb, int tid, float acc[4][8][4],
    uint32_t aoff, uint32_t boff)
{
    constexpr int T = KTOT / 32;

    auto load_tile = [&](int t, int s) {
        uint32_t ab = sb + s * STAGE_BYTES;
        uint32_t bb = ab + OPER_BYTES;
        int k0 = t * 32;
        #pragma unroll
        for (int i = 0; i < 4; i++) {          // 512 chunks each, 4/thread
            int idx = tid + i * 128;
            int row = idx >> 2, part = idx & 3;
            uint32_t doff = (uint32_t)(row * 80 + part * 16);
            CP_ASYNC16(ab + doff, Ag + (size_t)row * KTOT + k0 + part * 8);
            CP_ASYNC16(bb + doff, Bg + (size_t)row * KTOT + k0 + part * 8);
        }
    };

    load_tile(0, 0); CP_COMMIT();
    load_tile(1, 1); CP_COMMIT();

    int s = 0;
    for (int t = 0; t < T; t++) {
        CP_WAIT1();           // tile t resident (t+1 may be in flight)
        __syncthreads();      // visibility; slot s+2 reusable
        int lt = t + 2;
        int ls = s + 2; if (ls >= NSTAGE) ls -= NSTAGE;
        if (lt < T) load_tile(lt, ls);
        CP_COMMIT();

        uint32_t ab = sb + s * STAGE_BYTES + aoff;
        uint32_t bb = sb + s * STAGE_BYTES + OPER_BYTES + boff;
        #pragma unroll
        for (int ks = 0; ks < 2; ks++) {       // two k16 steps (+32 B each)
            uint32_t af[4][4], bf[8][2];
            #pragma unroll
            for (int mf = 0; mf < 4; mf++) {
                uint32_t base = ab + mf * (16 * 80) + ks * 32;
                af[mf][0] = lds32(base);
                af[mf][1] = lds32(base + 8 * 80);
                af[mf][2] = lds32(base + 16);
                af[mf][3] = lds32(base + 8 * 80 + 16);
            }
            #pragma unroll
            for (int nf = 0; nf < 8; nf++) {
                uint32_t base = bb + nf * (8 * 80) + ks * 32;
                bf[nf][0] = lds32(base);
                bf[nf][1] = lds32(base + 16);
            }
            #pragma unroll
            for (int mf = 0; mf < 4; mf++)
                #pragma unroll
                for (int nf = 0; nf < 8; nf++)
                    mma_f16(acc[mf][nf], af[mf], bf[nf]);
        }
        if (++s >= NSTAGE) s -= NSTAGE;
    }
}

// ---------------------------------------------------------------------------
// GEMM A (attention): cross tile 128x128 of masked F0 @ F1^T (K=512)
// -> A = 1/(1+sqrt(max(sq0+sq1-2*cross,0))) -> g_Ah, g_Ath
// ---------------------------------------------------------------------------
__global__ __launch_bounds__(128) void gemm_attn(void)
{
    extern __shared__ char smem[];
    const int tid = threadIdx.x;
    const int wid = tid >> 5, lane = tid & 31;
    const int g = lane >> 2, t4 = lane & 3;
    const int wm = wid & 1, wn = wid >> 1;     // 2 x 2 warp grid
    const int b = blockIdx.z, mt = blockIdx.y, nt = blockIdx.x;

    uint32_t sb = smem_u32(smem);
    const __half* Ag = g_F0h + (size_t)b * SS * DD + (size_t)mt * 128 * DD;
    const __half* Bg = g_F1h + (size_t)b * SS * DD + (size_t)nt * 128 * DD;

    float acc[4][8][4];
    #pragma unroll
    for (int i = 0; i < 4; i++)
        #pragma unroll
        for (int j = 0; j < 8; j++)
            #pragma unroll
            for (int r = 0; r < 4; r++) acc[i][j][r] = 0.f;

    const uint32_t aoff = (uint32_t)((wm * 64 + g) * 80 + t4 * 4);
    const uint32_t boff = (uint32_t)((wn * 64 + g) * 80 + t4 * 4);

    gemm_mainloop<512>(Ag, Bg, sb, tid, acc, aoff, boff);

    // -------------------- attention epilogue (two 64-row halves) ------------
    float* tile = (float*)smem;                         // [64][132] = 33792 B
    float* s_sq0 = (float*)(smem + 33792);              // [128]
    float* s_sq1 = s_sq0 + 128;                         // [128]

    __syncthreads();   // mainloop smem dead
    {
        s_sq0[tid] = g_sq0[b * SS + mt * 128 + tid];
        s_sq1[tid] = g_sq1[b * SS + nt * 128 + tid];
    }

    __half* Aout  = g_Ah  + (size_t)b * SS * SS;
    __half* Atout = g_Ath + (size_t)b * SS * SS;

    #pragma unroll 1
    for (int h = 0; h < 2; h++) {
        __syncthreads();
        if (wm == h) {
            #pragma unroll
            for (int mf = 0; mf < 4; mf++) {
                int lr = mf * 16 + g;
                #pragma unroll
                for (int nf = 0; nf < 8; nf++) {
                    int col = wn * 64 + nf * 8 + 2 * t4;
                    *(float2*)&tile[lr * 132 + col] =
                        make_float2(acc[mf][nf][0], acc[mf][nf][1]);
                    *(float2*)&tile[(lr + 8) * 132 + col] =
                        make_float2(acc[mf][nf][2], acc[mf][nf][3]);
                }
            }
        }
        __syncthreads();

        #pragma unroll
        for (int it = 0; it < 16; it++) {
            int lin = it * 512 + tid * 4;
            int row = lin >> 7, col = lin & 127;
            int grow = h * 64 + row;
            float s0v = s_sq0[grow];
            float4 cr = *(float4*)&tile[row * 132 + col];
            float d2, v0, v1, v2, v3;
            d2 = fmaxf(s0v + s_sq1[col]     - 2.f * cr.x, 0.f);
            v0 = 1.f / (1.f + sqrtf(d2));
            d2 = fmaxf(s0v + s_sq1[col + 1] - 2.f * cr.y, 0.f);
            v1 = 1.f / (1.f + sqrtf(d2));
            d2 = fmaxf(s0v + s_sq1[col + 2] - 2.f * cr.z, 0.f);
            v2 = 1.f / (1.f + sqrtf(d2));
            d2 = fmaxf(s0v + s_sq1[col + 3] - 2.f * cr.w, 0.f);
            v3 = 1.f / (1.f + sqrtf(d2));
            size_t idx = (size_t)(mt * 128 + grow) * SS + nt * 128 + col;
            *(__half2*)&Aout[idx]     = __floats2half2_rn(v0, v1);
            *(__half2*)&Aout[idx + 2] = __floats2half2_rn(v2, v3);
        }

        #pragma unroll
        for (int it = 0; it < 16; it++) {
            int pair = it * 128 + tid;
            int col = pair >> 4, rg = pair & 15;
            int r0 = rg * 4;
            float s1v = s_sq1[col];
            float v[4];
            #pragma unroll
            for (int q = 0; q < 4; q++) {
                int row = r0 + q, grow = h * 64 + row;
                float cr = tile[row * 132 + col];
                float d2 = fmaxf(s_sq0[grow] + s1v - 2.f * cr, 0.f);
                v[q] = 1.f / (1.f + sqrtf(d2));
            }
            size_t idx = (size_t)(nt * 128 + col) * SS + mt * 128 + h * 64 + r0;
            *(__half2*)&Atout[idx]     = __floats2half2_rn(v[0], v[1]);
            *(__half2*)&Atout[idx + 2] = __floats2half2_rn(v[2], v[3]);
        }
    }
}

// ---------------------------------------------------------------------------
// FUSED GEMM B + conv.  blockIdx.y: sel = y>>1 (0:F0a, 1:F1a), mt = y&1.
// Mainloop: Fa tile 128(s) x 128(d), fp32 acc.  Epilogue: stage Fa as fp16
// in smem (pitch 136 halfs, conflict-free), dump 8 boundary rows to global,
// then rolling-window conv+tanh+pool down each column writing out rows
// local 2..125 directly.  Boundary out rows handled by conv_edge.
// ---------------------------------------------------------------------------
#define FA_PITCH 136

__global__ __launch_bounds__(128) void gemm_aggr_conv(
    const float* __restrict__ conv_w, const float* __restrict__ conv_b,
    float* __restrict__ out)
{
    extern __shared__ char smem[];
    const int tid = threadIdx.x;
    const int wid = tid >> 5, lane = tid & 31;
    const int g = lane >> 2, t4 = lane & 3;
    const int wm = wid & 1, wn = wid >> 1;
    const int b = blockIdx.z, nt = blockIdx.x;
    const int sel = blockIdx.y >> 1;          // 0: F0a, 1: F1a
    const int mt  = blockIdx.y & 1;

    uint32_t sb = smem_u32(smem);
    const __half* Ag = (sel ? g_Ah : g_Ath) + (size_t)b * SS * SS + (size_t)mt * 128 * SS;
    const __half* Bg = (sel ? g_W1th : g_W0th) + (size_t)nt * 128 * SS;

    float acc[4][8][4];
    #pragma unroll
    for (int i = 0; i < 4; i++)
        #pragma unroll
        for (int j = 0; j < 8; j++)
            #pragma unroll
            for (int r = 0; r < 4; r++) acc[i][j][r] = 0.f;

    const uint32_t aoff = (uint32_t)((wm * 64 + g) * 80 + t4 * 4);
    const uint32_t boff = (uint32_t)((wn * 64 + g) * 80 + t4 * 4);

    gemm_mainloop<256>(Ag, Bg, sb, tid, acc, aoff, boff);

    // ---- stage Fa tile to smem as fp16 ----
    __half* sh = (__half*)smem;
    __syncthreads();   // mainloop smem dead
    #pragma unroll
    for (int mf = 0; mf < 4; mf++) {
        int row = wm * 64 + mf * 16 + g;
        #pragma unroll
        for (int nf = 0; nf < 8; nf++) {
            int col = wn * 64 + nf * 8 + 2 * t4;
            *(__half2*)&sh[row * FA_PITCH + col] =
                __floats2half2_rn(acc[mf][nf][0], acc[mf][nf][1]);
            *(__half2*)&sh[(row + 8) * FA_PITCH + col] =
                __floats2half2_rn(acc[mf][nf][2], acc[mf][nf][3]);
        }
    }
    __syncthreads();

    // ---- dump 8 boundary Fa rows (local 0..3, 124..127) to global ----
    {
        __half* Fah = (sel ? g_F1ah : g_F0ah) + (size_t)b * SS * DD;
        #pragma unroll
        for (int idx = tid; idx < 512; idx += 128) {     // 8 rows x 64 half2
            int rr = idx >> 6;
            int row = (rr < 4) ? rr : (120 + rr);
            int cp = (idx & 63) * 2;
            __half2 v = *(__half2*)&sh[row * FA_PITCH + cp];
            *(__half2*)&Fah[(size_t)(mt * 128 + row) * DD + nt * 128 + cp] = v;
        }
    }

    // ---- fused conv + tanh + pool (interior rows local 2..125) ----
    const float w00 = conv_w[0], w01 = conv_w[1], w02 = conv_w[2];
    const float w10 = conv_w[3], w11 = conv_w[4], w12 = conv_w[5];
    const float cb  = conv_b[0];

    const __half* Fp = (sel ? g_F1h : g_F0h)
        + ((size_t)b * SS + mt * 128) * DD + nt * 128 + tid;
    float* op = out + ((size_t)sel * BB + b) * SS * DD
        + (size_t)(mt * 128) * DD + nt * 128 + tid;

    float aA = 0.f, aB = 0.f, pA = 0.f, pB = 0.f;
    #pragma unroll 1
    for (int blk = 0; blk < 8; blk++) {
        float xfb[16];
        #pragma unroll
        for (int j = 0; j < 16; j++)
            xfb[j] = __half2float(Fp[(size_t)(blk * 16 + j) * DD]);
        #pragma unroll
        for (int j = 0; j < 16; j++) {
            int r = blk * 16 + j;
            float xf = xfb[j];
            float xa = __half2float(sh[r * FA_PITCH + tid]);
            if (r >= 2) {
                float y = tanh_fast(aA + w02 * xf + w12 * xa);
                if (r >= 4)
                    op[(size_t)(r - 2) * DD] = (pA + y) * (1.f / 3.f);
                pA = pB + y;
                pB = y;
            }
            aA = aB + w01 * xf + w11 * xa;
            aB = cb + w00 * xf + w10 * xa;
        }
    }
}

// ---------------------------------------------------------------------------
// conv_edge: boundary out rows {0,1,126,127,128,129,254,255} per (b,sel).
// Reads F (full fp16) and the boundary Fa rows dumped by gemm_aggr_conv.
// ---------------------------------------------------------------------------
__global__ __launch_bounds__(512) void conv_edge(
    const float* __restrict__ conv_w, const float* __restrict__ conv_b,
    float* __restrict__ out)
{
    const int sel = blockIdx.x & 1;
    const int b   = blockIdx.x >> 1;
    const int d   = threadIdx.x;
    const __half* F  = (sel ? g_F1h : g_F0h) + (size_t)b * SS * DD + d;
    const __half* Fa = (sel ? g_F1ah : g_F0ah) + (size_t)b * SS * DD + d;
    float* o = out + ((size_t)sel * BB + b) * SS * DD + d;

    const float w0 = conv_w[0], w1 = conv_w[1], w2 = conv_w[2];
    const float u0 = conv_w[3], u1 = conv_w[4], u2 = conv_w[5];
    const float cb = conv_b[0];
    const float wh[3] = {w0, w1, w2};
    const float uh[3] = {u0, u1, u2};

    const int rows[8] = {0, 1, 126, 127, 128, 129, 254, 255};
    #pragma unroll
    for (int k = 0; k < 8; k++) {
        int s = rows[k];
        float acc = 0.f;
        #pragma unroll
        for (int vv = 0; vv < 3; vv++) {
            int v = s - 2 + vv;
            float z = cb;
            #pragma unroll
            for (int h = 0; h < 3; h++) {
                int r = v + h;
                if (r >= 0 && r < SS)
                    z += wh[h] * __half2float(F[(size_t)r * DD])
                       + uh[h] * __half2float(Fa[(size_t)r * DD]);
            }
            acc += tanh_fast(z);
        }
        o[(size_t)s * DD] = acc * (1.f / 3.f);
    }
}

// ---------------------------------------------------------------------------
// Launch
// ---------------------------------------------------------------------------
extern "C" void kernel_launch(void* const* d_in, const int* in_sizes, int n_in,
                              void* d_out, int out_size)
{
    const float* F0r    = (const float*)d_in[0];
    const float* F1r    = (const float*)d_in[1];
    const float* m0     = (const float*)d_in[2];
    const float* m1     = (const float*)d_in[3];
    const float* W0     = (const float*)d_in[4];
    const float* W1     = (const float*)d_in[5];
    const float* conv_w = (const float*)d_in[6];
    const float* conv_b = (const float*)d_in[7];
    float* out = (float*)d_out;

    cudaFuncSetAttribute(gemm_attn, cudaFuncAttributeMaxDynamicSharedMemorySize, GEMM_SMEM);
    cudaFuncSetAttribute(gemm_aggr_conv, cudaFuncAttributeMaxDynamicSharedMemorySize, GEMM_SMEM);

    prep_kernel<<<8448, 256>>>(F0r, F1r, m0, m1, W0, W1);

    gemm_attn<<<dim3(2, 2, BB), 128, GEMM_SMEM>>>();
    gemm_aggr_conv<<<dim3(4, 4, BB), 128, GEMM_SMEM>>>(conv_w, conv_b, out);
    conv_edge<<<2 * BB, 512>>>(conv_w, conv_b, out);
}